// round 1
// baseline (speedup 1.0000x reference)
#include <cuda_runtime.h>
#include <cuda_bf16.h>

// Problem constants
#define BB   2
#define TT   2048
#define DD   1024
#define HH   16
#define DH   64
#define CC   64           // chunk size
#define NC   32           // TT / CC
#define BH   32           // BB * HH
#define MM   4096         // BB * TT
#define EPSF 1e-6f

// Scratch (device globals; allocation is forbidden)
__device__ float g_q[BH * TT * DH];        // [b,h,t,dh]
__device__ float g_k[BH * TT * DH];
__device__ float g_v[BH * TT * DH];
__device__ float g_att[MM * DD];           // [b,t,h*dh]
__device__ float g_kv[BH * NC * DH * DH];  // per-chunk KV, then exclusive prefix
__device__ float g_ks[BH * NC * DH];       // per-chunk k-sum, then exclusive prefix

// ---------------------------------------------------------------------------
// GEMM: out[m,n] = sum_k X[m,k] * Wt[n,k] + bias[n]
// 64x64 block tile, 256 threads, 4x4 per thread, BK=16, fp32.
// apply_fm: elu(x)+1 feature map. head_layout: write to [b,h,t,dh] layout.
// ---------------------------------------------------------------------------
__global__ __launch_bounds__(256) void gemm64(
    const float* __restrict__ X, const float* __restrict__ Wt,
    const float* __restrict__ bias, float* __restrict__ out,
    int apply_fm, int head_layout)
{
    __shared__ float As[16][68];   // [kk][row], padded: float4-aligned, <=2-way conflicts
    __shared__ float Bs[16][68];

    const int tid = threadIdx.x;
    const int tx = tid & 15, ty = tid >> 4;
    const int m0 = blockIdx.y * 64, n0 = blockIdx.x * 64;
    const int lr = tid >> 2;          // 0..63 row within tile
    const int lk = (tid & 3) << 2;    // 0,4,8,12

    float acc[4][4] = {};

    const float* xp = X  + (size_t)(m0 + lr) * DD + lk;
    const float* wp = Wt + (size_t)(n0 + lr) * DD + lk;

    for (int kb = 0; kb < DD; kb += 16) {
        float4 av = *(const float4*)(xp + kb);
        float4 bv = *(const float4*)(wp + kb);
        As[lk + 0][lr] = av.x; As[lk + 1][lr] = av.y;
        As[lk + 2][lr] = av.z; As[lk + 3][lr] = av.w;
        Bs[lk + 0][lr] = bv.x; Bs[lk + 1][lr] = bv.y;
        Bs[lk + 2][lr] = bv.z; Bs[lk + 3][lr] = bv.w;
        __syncthreads();
        #pragma unroll
        for (int kk = 0; kk < 16; kk++) {
            float4 a = *(const float4*)&As[kk][ty * 4];
            float4 b = *(const float4*)&Bs[kk][tx * 4];
            acc[0][0] += a.x * b.x; acc[0][1] += a.x * b.y; acc[0][2] += a.x * b.z; acc[0][3] += a.x * b.w;
            acc[1][0] += a.y * b.x; acc[1][1] += a.y * b.y; acc[1][2] += a.y * b.z; acc[1][3] += a.y * b.w;
            acc[2][0] += a.z * b.x; acc[2][1] += a.z * b.y; acc[2][2] += a.z * b.z; acc[2][3] += a.z * b.w;
            acc[3][0] += a.w * b.x; acc[3][1] += a.w * b.y; acc[3][2] += a.w * b.z; acc[3][3] += a.w * b.w;
        }
        __syncthreads();
    }

    #pragma unroll
    for (int i = 0; i < 4; i++) {
        const int row = m0 + ty * 4 + i;
        float4 r;
        float* rp = &r.x;
        #pragma unroll
        for (int j = 0; j < 4; j++) {
            const int col = n0 + tx * 4 + j;
            float vv = acc[i][j] + bias[col];
            if (apply_fm) vv = (vv > 0.f) ? (vv + 1.f) : expf(vv);
            rp[j] = vv;
        }
        if (head_layout) {
            const int b = row >> 11, t = row & (TT - 1), h = n0 >> 6;
            *(float4*)&out[((size_t)(b * HH + h) * TT + t) * DH + tx * 4] = r;
        } else {
            *(float4*)&out[(size_t)row * DD + n0 + tx * 4] = r;
        }
    }
}

// ---------------------------------------------------------------------------
// Per-chunk stats: KV_c[d][e] = sum_t k[t][d] * v[t][e];  ksum_c[d] = sum_t k[t][d]
// One CTA per (chunk, bh). 256 threads, 4x4 per thread for the 64x64 output.
// ---------------------------------------------------------------------------
__global__ __launch_bounds__(256) void chunk_kv()
{
    __shared__ float ks[64][64];  // [t][d]
    __shared__ float vs[64][64];  // [t][e]
    const int c = blockIdx.x, bh = blockIdx.y;
    const int tid = threadIdx.x, tx = tid & 15, ty = tid >> 4;

    const float4* kp = (const float4*)(g_k + ((size_t)bh * TT + c * 64) * DH);
    const float4* vp = (const float4*)(g_v + ((size_t)bh * TT + c * 64) * DH);
    for (int i = tid; i < 1024; i += 256) {
        ((float4*)ks)[i] = kp[i];
        ((float4*)vs)[i] = vp[i];
    }
    __syncthreads();

    float acc[4][4] = {};
    #pragma unroll 8
    for (int t = 0; t < 64; t++) {
        float4 a = *(const float4*)&ks[t][ty * 4];
        float4 b = *(const float4*)&vs[t][tx * 4];
        acc[0][0] += a.x * b.x; acc[0][1] += a.x * b.y; acc[0][2] += a.x * b.z; acc[0][3] += a.x * b.w;
        acc[1][0] += a.y * b.x; acc[1][1] += a.y * b.y; acc[1][2] += a.y * b.z; acc[1][3] += a.y * b.w;
        acc[2][0] += a.z * b.x; acc[2][1] += a.z * b.y; acc[2][2] += a.z * b.z; acc[2][3] += a.z * b.w;
        acc[3][0] += a.w * b.x; acc[3][1] += a.w * b.y; acc[3][2] += a.w * b.z; acc[3][3] += a.w * b.w;
    }

    float* kvout = g_kv + ((size_t)bh * NC + c) * 4096;
    #pragma unroll
    for (int i = 0; i < 4; i++) {
        float4 r = make_float4(acc[i][0], acc[i][1], acc[i][2], acc[i][3]);
        *(float4*)&kvout[(ty * 4 + i) * 64 + tx * 4] = r;
    }
    if (tid < 64) {
        float s = 0.f;
        #pragma unroll 8
        for (int t = 0; t < 64; t++) s += ks[t][tid];
        g_ks[((size_t)bh * NC + c) * 64 + tid] = s;
    }
}

// ---------------------------------------------------------------------------
// Exclusive prefix scan across chunks (per bh): in-place on g_kv / g_ks.
// ---------------------------------------------------------------------------
__global__ __launch_bounds__(256) void prefix_scan()
{
    const int bh = blockIdx.x;
    float* base = g_kv + (size_t)bh * NC * 4096;
    for (int p = threadIdx.x; p < 4096; p += 256) {
        float run = 0.f;
        #pragma unroll
        for (int c = 0; c < NC; c++) {
            float tmp = base[c * 4096 + p];
            base[c * 4096 + p] = run;
            run += tmp;
        }
    }
    if (threadIdx.x < 64) {
        float run = 0.f;
        float* kb = g_ks + (size_t)bh * NC * 64 + threadIdx.x;
        #pragma unroll
        for (int c = 0; c < NC; c++) {
            float tmp = kb[c * 64];
            kb[c * 64] = run;
            run += tmp;
        }
    }
}

// ---------------------------------------------------------------------------
// Per-chunk attention output:
//   A = mask(Q K^T);  out = (A V + Q S) / max(rowsum(A) + Q z, EPS)
// One CTA per (chunk, bh). 256 threads, 4x4 per thread.
// ---------------------------------------------------------------------------
__global__ __launch_bounds__(256) void attn_chunk()
{
    __shared__ float Qs[64 * 64];   // [r][d]
    __shared__ float KA[64 * 64];   // K^T [d][c], reused as A [r][t]
    __shared__ float VS[64 * 64];   // V [t][e], reused as S [d][e]

    const int c = blockIdx.x, bh = blockIdx.y;
    const int tid = threadIdx.x, tx = tid & 15, ty = tid >> 4;

    const float* qp = g_q + ((size_t)bh * TT + c * 64) * DH;
    const float* kp = g_k + ((size_t)bh * TT + c * 64) * DH;
    const float* vp = g_v + ((size_t)bh * TT + c * 64) * DH;

    for (int i = tid; i < 1024; i += 256) {
        ((float4*)Qs)[i] = ((const float4*)qp)[i];
        ((float4*)VS)[i] = ((const float4*)vp)[i];
        float4 kv4 = ((const float4*)kp)[i];
        const int r = i >> 4, d0 = (i & 15) << 2;  // transpose K -> [d][c]
        KA[(d0 + 0) * 64 + r] = kv4.x;
        KA[(d0 + 1) * 64 + r] = kv4.y;
        KA[(d0 + 2) * 64 + r] = kv4.z;
        KA[(d0 + 3) * 64 + r] = kv4.w;
    }
    __syncthreads();

    // A = Q K^T
    float a[4][4] = {};
    #pragma unroll 8
    for (int d = 0; d < 64; d++) {
        float q0 = Qs[(ty * 4 + 0) * 64 + d];
        float q1 = Qs[(ty * 4 + 1) * 64 + d];
        float q2 = Qs[(ty * 4 + 2) * 64 + d];
        float q3 = Qs[(ty * 4 + 3) * 64 + d];
        float4 kc = *(const float4*)&KA[d * 64 + tx * 4];
        a[0][0] += q0 * kc.x; a[0][1] += q0 * kc.y; a[0][2] += q0 * kc.z; a[0][3] += q0 * kc.w;
        a[1][0] += q1 * kc.x; a[1][1] += q1 * kc.y; a[1][2] += q1 * kc.z; a[1][3] += q1 * kc.w;
        a[2][0] += q2 * kc.x; a[2][1] += q2 * kc.y; a[2][2] += q2 * kc.z; a[2][3] += q2 * kc.w;
        a[3][0] += q3 * kc.x; a[3][1] += q3 * kc.y; a[3][2] += q3 * kc.z; a[3][3] += q3 * kc.w;
    }
    // causal mask (keep key index <= query index)
    #pragma unroll
    for (int i = 0; i < 4; i++)
        #pragma unroll
        for (int j = 0; j < 4; j++)
            if (tx * 4 + j > ty * 4 + i) a[i][j] = 0.f;

    // masked rowsum, butterfly across the 16 tx lanes (ty constant in each group)
    float rsum[4];
    #pragma unroll
    for (int i = 0; i < 4; i++) {
        float s = a[i][0] + a[i][1] + a[i][2] + a[i][3];
        #pragma unroll
        for (int off = 1; off < 16; off <<= 1)
            s += __shfl_xor_sync(0xffffffffu, s, off);
        rsum[i] = s;
    }

    __syncthreads();  // all K^T reads done, reuse KA for A [r][t]
    #pragma unroll
    for (int i = 0; i < 4; i++)
        *(float4*)&KA[(ty * 4 + i) * 64 + tx * 4] =
            make_float4(a[i][0], a[i][1], a[i][2], a[i][3]);
    __syncthreads();

    // acc = A @ V
    float acc[4][4] = {};
    #pragma unroll 8
    for (int t = 0; t < 64; t++) {
        float a0 = KA[(ty * 4 + 0) * 64 + t];
        float a1 = KA[(ty * 4 + 1) * 64 + t];
        float a2 = KA[(ty * 4 + 2) * 64 + t];
        float a3 = KA[(ty * 4 + 3) * 64 + t];
        float4 vv = *(const float4*)&VS[t * 64 + tx * 4];
        acc[0][0] += a0 * vv.x; acc[0][1] += a0 * vv.y; acc[0][2] += a0 * vv.z; acc[0][3] += a0 * vv.w;
        acc[1][0] += a1 * vv.x; acc[1][1] += a1 * vv.y; acc[1][2] += a1 * vv.z; acc[1][3] += a1 * vv.w;
        acc[2][0] += a2 * vv.x; acc[2][1] += a2 * vv.y; acc[2][2] += a2 * vv.z; acc[2][3] += a2 * vv.w;
        acc[3][0] += a3 * vv.x; acc[3][1] += a3 * vv.y; acc[3][2] += a3 * vv.z; acc[3][3] += a3 * vv.w;
    }
    __syncthreads();  // V reads done, reuse VS for S

    const float4* sp = (const float4*)(g_kv + ((size_t)bh * NC + c) * 4096);
    for (int i = tid; i < 1024; i += 256) ((float4*)VS)[i] = sp[i];
    __syncthreads();

    const float* zp = g_ks + ((size_t)bh * NC + c) * 64;
    float qz[4] = {};
    #pragma unroll 8
    for (int d = 0; d < 64; d++) {
        float q0 = Qs[(ty * 4 + 0) * 64 + d];
        float q1 = Qs[(ty * 4 + 1) * 64 + d];
        float q2 = Qs[(ty * 4 + 2) * 64 + d];
        float q3 = Qs[(ty * 4 + 3) * 64 + d];
        float4 sv = *(const float4*)&VS[d * 64 + tx * 4];
        float z = zp[d];
        acc[0][0] += q0 * sv.x; acc[0][1] += q0 * sv.y; acc[0][2] += q0 * sv.z; acc[0][3] += q0 * sv.w;
        acc[1][0] += q1 * sv.x; acc[1][1] += q1 * sv.y; acc[1][2] += q1 * sv.z; acc[1][3] += q1 * sv.w;
        acc[2][0] += q2 * sv.x; acc[2][1] += q2 * sv.y; acc[2][2] += q2 * sv.z; acc[2][3] += q2 * sv.w;
        acc[3][0] += q3 * sv.x; acc[3][1] += q3 * sv.y; acc[3][2] += q3 * sv.z; acc[3][3] += q3 * sv.w;
        qz[0] += q0 * z; qz[1] += q1 * z; qz[2] += q2 * z; qz[3] += q3 * z;
    }

    const int b = bh >> 4, h = bh & 15;
    #pragma unroll
    for (int i = 0; i < 4; i++) {
        const float den = fmaxf(rsum[i] + qz[i], EPSF);
        const float inv = 1.0f / den;
        const int tg = c * 64 + ty * 4 + i;
        float4 o = make_float4(acc[i][0] * inv, acc[i][1] * inv,
                               acc[i][2] * inv, acc[i][3] * inv);
        *(float4*)&g_att[((size_t)(b * TT + tg)) * DD + h * 64 + tx * 4] = o;
    }
}

// ---------------------------------------------------------------------------
extern "C" void kernel_launch(void* const* d_in, const int* in_sizes, int n_in,
                              void* d_out, int out_size)
{
    const float* x  = (const float*)d_in[0];
    const float* Wq = (const float*)d_in[1];
    const float* bq = (const float*)d_in[2];
    const float* Wk = (const float*)d_in[3];
    const float* bk = (const float*)d_in[4];
    const float* Wv = (const float*)d_in[5];
    const float* bv = (const float*)d_in[6];
    const float* Wo = (const float*)d_in[7];
    const float* bo = (const float*)d_in[8];
    float* out = (float*)d_out;

    float *q, *k, *v, *att;
    cudaGetSymbolAddress((void**)&q,   g_q);
    cudaGetSymbolAddress((void**)&k,   g_k);
    cudaGetSymbolAddress((void**)&v,   g_v);
    cudaGetSymbolAddress((void**)&att, g_att);

    dim3 gg(DD / 64, MM / 64);
    gemm64<<<gg, 256>>>(x, Wq, bq, q, 1, 1);
    gemm64<<<gg, 256>>>(x, Wk, bk, k, 1, 1);
    gemm64<<<gg, 256>>>(x, Wv, bv, v, 0, 1);
    chunk_kv<<<dim3(NC, BH), 256>>>();
    prefix_scan<<<BH, 256>>>();
    attn_chunk<<<dim3(NC, BH), 256>>>();
    gemm64<<<gg, 256>>>(att, Wo, bo, out, 0, 0);
}

// round 3
// speedup vs baseline: 2.0570x; 2.0570x over previous
#include <cuda_runtime.h>
#include <cuda_bf16.h>
#include <cstdint>

// Problem constants
#define BB   2
#define TT   2048
#define DD   1024
#define HH   16
#define DH   64
#define NC   32           // TT / 64 chunks
#define BH   32           // BB * HH
#define MM   4096         // BB * TT
#define EPSF 1e-6f

// GEMM tiling
#define BM   128
#define BN   128
#define BK   32
#define NKB  (DD / BK)    // 32 k-stages
#define ROWB 72           // padded row stride in bytes (36 bf16) -> conflict-free frags
#define TILE_A 9216       // 128 rows * 72 B
#define STAGE  (4 * TILE_A)      // Ahi | Alo | Bhi | Blo
#define SMEM_DYN (2 * STAGE)     // double buffered = 73728 B

// Scratch (device globals; allocation is forbidden)
__device__ float g_q[BH * TT * DH];        // [b,h,t,dh]
__device__ float g_k[BH * TT * DH];
__device__ float g_v[BH * TT * DH];
__device__ float g_att[MM * DD];           // [b,t,h*dh]
__device__ float g_kv[BH * NC * DH * DH];  // per-chunk KV, then exclusive prefix
__device__ float g_ks[BH * NC * DH];       // per-chunk k-sum, then exclusive prefix

// ---------------------------------------------------------------------------
// helpers
// ---------------------------------------------------------------------------
__device__ __forceinline__ uint32_t smem_u32(const void* p) {
    uint32_t a;
    asm("{ .reg .u64 t; cvta.to.shared.u64 t, %1; cvt.u32.u64 %0, t; }"
        : "=r"(a) : "l"(p));
    return a;
}
__device__ __forceinline__ uint32_t lds32(uint32_t a) {
    uint32_t v;
    asm volatile("ld.shared.b32 %0, [%1];" : "=r"(v) : "r"(a));
    return v;
}
__device__ __forceinline__ void sts64(uint32_t a, uint32_t x, uint32_t y) {
    asm volatile("st.shared.v2.b32 [%0], {%1, %2};" :: "r"(a), "r"(x), "r"(y) : "memory");
}
__device__ __forceinline__ uint32_t packbf2(__nv_bfloat16 lo, __nv_bfloat16 hi) {
    __nv_bfloat162 h = __halves2bfloat162(lo, hi);
    return *(uint32_t*)&h;
}
__device__ __forceinline__ void mma16816(float* c, const uint32_t* a, const uint32_t* b) {
    asm volatile(
        "mma.sync.aligned.m16n8k16.row.col.f32.bf16.bf16.f32 "
        "{%0,%1,%2,%3}, {%4,%5,%6,%7}, {%8,%9}, {%0,%1,%2,%3};"
        : "+f"(c[0]), "+f"(c[1]), "+f"(c[2]), "+f"(c[3])
        : "r"(a[0]), "r"(a[1]), "r"(a[2]), "r"(a[3]), "r"(b[0]), "r"(b[1]));
}

// ---------------------------------------------------------------------------
// Split-bf16 tensor-core GEMM: out[m][n] = fm( sum_k X[m][k]*Wt[n][k] + bias[n] )
// 128x128 CTA tile, BK=32, 8 warps (2x4), warp tile 64x32, mma.m16n8k16.bf16.
// 3-term split (hi*hi + hi*lo + lo*hi) with fp32 accumulation: rel err ~1e-5.
// blockIdx.z selects one of up to 3 weight sets (QKV fusion).
// ---------------------------------------------------------------------------
__global__ __launch_bounds__(256, 1) void mma_gemm(
    const float* __restrict__ X,
    const float* __restrict__ W0, const float* __restrict__ b0, float* __restrict__ o0, int f0,
    const float* __restrict__ W1, const float* __restrict__ b1, float* __restrict__ o1, int f1,
    const float* __restrict__ W2, const float* __restrict__ b2, float* __restrict__ o2, int f2,
    int head_layout)
{
    extern __shared__ char dsm[];

    const int z = blockIdx.z;
    const float* Wt   = (z == 0) ? W0 : (z == 1) ? W1 : W2;
    const float* bias = (z == 0) ? b0 : (z == 1) ? b1 : b2;
    float*       outp = (z == 0) ? o0 : (z == 1) ? o1 : o2;
    const int    fm   = (z == 0) ? f0 : (z == 1) ? f1 : f2;

    const int tid  = threadIdx.x;
    const int wid  = tid >> 5, lane = tid & 31;
    const int m0   = blockIdx.y * BM, n0 = blockIdx.x * BN;
    const int wm   = (wid >> 2) * 64, wn = (wid & 3) * 32;
    const int g    = lane >> 2, tig = lane & 3;
    const uint32_t sb = smem_u32(dsm);

    float acc[4][4][4];
    #pragma unroll
    for (int i = 0; i < 4; i++)
        #pragma unroll
        for (int j = 0; j < 4; j++)
            #pragma unroll
            for (int q = 0; q < 4; q++) acc[i][j][q] = 0.f;

    // staging: each thread handles 4 float4 of A and 4 of B per stage
    const int srow = tid >> 3;            // 0..31 (+ i*32)
    const int sc4  = (tid & 7) << 2;      // element col 0,4,...,28
    const float* xp = X  + (size_t)(m0 + srow) * DD + sc4;
    const float* wp = Wt + (size_t)(n0 + srow) * DD + sc4;

    float4 ra[4], rb[4];

    auto gload = [&](int kb) {
        #pragma unroll
        for (int i = 0; i < 4; i++) {
            ra[i] = *(const float4*)(xp + (size_t)(i * 32) * DD + kb);
            rb[i] = *(const float4*)(wp + (size_t)(i * 32) * DD + kb);
        }
    };

    auto sstore = [&](int s) {
        const uint32_t base = sb + s * STAGE;
        #pragma unroll
        for (int i = 0; i < 4; i++) {
            const uint32_t off = (uint32_t)(srow + i * 32) * ROWB + sc4 * 2;
            // A hi/lo
            {
                float4 v = ra[i];
                __nv_bfloat16 h0 = __float2bfloat16(v.x), h1 = __float2bfloat16(v.y);
                __nv_bfloat16 h2 = __float2bfloat16(v.z), h3 = __float2bfloat16(v.w);
                __nv_bfloat16 l0 = __float2bfloat16(v.x - __bfloat162float(h0));
                __nv_bfloat16 l1 = __float2bfloat16(v.y - __bfloat162float(h1));
                __nv_bfloat16 l2 = __float2bfloat16(v.z - __bfloat162float(h2));
                __nv_bfloat16 l3 = __float2bfloat16(v.w - __bfloat162float(h3));
                sts64(base + off,          packbf2(h0, h1), packbf2(h2, h3));
                sts64(base + TILE_A + off, packbf2(l0, l1), packbf2(l2, l3));
            }
            // B hi/lo
            {
                float4 v = rb[i];
                __nv_bfloat16 h0 = __float2bfloat16(v.x), h1 = __float2bfloat16(v.y);
                __nv_bfloat16 h2 = __float2bfloat16(v.z), h3 = __float2bfloat16(v.w);
                __nv_bfloat16 l0 = __float2bfloat16(v.x - __bfloat162float(h0));
                __nv_bfloat16 l1 = __float2bfloat16(v.y - __bfloat162float(h1));
                __nv_bfloat16 l2 = __float2bfloat16(v.z - __bfloat162float(h2));
                __nv_bfloat16 l3 = __float2bfloat16(v.w - __bfloat162float(h3));
                sts64(base + 2 * TILE_A + off, packbf2(h0, h1), packbf2(h2, h3));
                sts64(base + 3 * TILE_A + off, packbf2(l0, l1), packbf2(l2, l3));
            }
        }
    };

    auto compute = [&](int s) {
        const uint32_t base = sb + s * STAGE;
        #pragma unroll
        for (int kt = 0; kt < 2; kt++) {
            const uint32_t kb = (uint32_t)(tig * 4 + kt * 32);
            // B fragments for all 4 n-tiles (hi + lo)
            uint32_t bh[4][2], bl[4][2];
            #pragma unroll
            for (int nt = 0; nt < 4; nt++) {
                const uint32_t r = (uint32_t)(wn + nt * 8 + g);
                const uint32_t o = base + 2 * TILE_A + r * ROWB + kb;
                bh[nt][0] = lds32(o);           bh[nt][1] = lds32(o + 16);
                bl[nt][0] = lds32(o + TILE_A);  bl[nt][1] = lds32(o + TILE_A + 16);
            }
            #pragma unroll
            for (int mt = 0; mt < 4; mt++) {
                const uint32_t r = (uint32_t)(wm + mt * 16 + g);
                const uint32_t o = base + r * ROWB + kb;
                uint32_t ah[4], al[4];
                ah[0] = lds32(o);                  ah[1] = lds32(o + 8 * ROWB);
                ah[2] = lds32(o + 16);             ah[3] = lds32(o + 8 * ROWB + 16);
                al[0] = lds32(o + TILE_A);         al[1] = lds32(o + TILE_A + 8 * ROWB);
                al[2] = lds32(o + TILE_A + 16);    al[3] = lds32(o + TILE_A + 8 * ROWB + 16);
                #pragma unroll
                for (int nt = 0; nt < 4; nt++) {
                    mma16816(acc[mt][nt], ah, bh[nt]);
                    mma16816(acc[mt][nt], ah, bl[nt]);
                    mma16816(acc[mt][nt], al, bh[nt]);
                }
            }
        }
    };

    gload(0);
    sstore(0);
    __syncthreads();

    for (int c = 0; c < NKB; c++) {
        const int s = c & 1;
        if (c + 1 < NKB) gload((c + 1) * BK);
        compute(s);
        if (c + 1 < NKB) {
            sstore(s ^ 1);
            __syncthreads();
        }
    }

    // Epilogue: bias + optional ELU+1 feature map + store (float2 per frag row)
    const int hcol = (n0 + wn) >> 6;   // head index (constant per warp, head_layout)
    #pragma unroll
    for (int mt = 0; mt < 4; mt++) {
        const int r0 = m0 + wm + mt * 16 + g;
        #pragma unroll
        for (int nt = 0; nt < 4; nt++) {
            const int cn = n0 + wn + nt * 8 + 2 * tig;
            float v0 = acc[mt][nt][0] + bias[cn];
            float v1 = acc[mt][nt][1] + bias[cn + 1];
            float v2 = acc[mt][nt][2] + bias[cn];
            float v3 = acc[mt][nt][3] + bias[cn + 1];
            if (fm) {
                v0 = (v0 > 0.f) ? (v0 + 1.f) : expf(v0);
                v1 = (v1 > 0.f) ? (v1 + 1.f) : expf(v1);
                v2 = (v2 > 0.f) ? (v2 + 1.f) : expf(v2);
                v3 = (v3 > 0.f) ? (v3 + 1.f) : expf(v3);
            }
            if (head_layout) {
                const int b = r0 >> 11, t = r0 & (TT - 1);
                const int dh = cn & 63;
                float* p = outp + ((size_t)((b * HH + hcol) * TT + t)) * DH + dh;
                *(float2*)p              = make_float2(v0, v1);
                *(float2*)(p + 8 * DH)   = make_float2(v2, v3);
            } else {
                float* p = outp + (size_t)r0 * DD + cn;
                *(float2*)p              = make_float2(v0, v1);
                *(float2*)(p + 8 * DD)   = make_float2(v2, v3);
            }
        }
    }
}

// ---------------------------------------------------------------------------
// Per-chunk stats: KV_c[d][e] = sum_t k[t][d] * v[t][e];  ksum_c[d] = sum_t k[t][d]
// ---------------------------------------------------------------------------
__global__ __launch_bounds__(256) void chunk_kv()
{
    __shared__ float ks[64][64];
    __shared__ float vs[64][64];
    const int c = blockIdx.x, bh = blockIdx.y;
    const int tid = threadIdx.x, tx = tid & 15, ty = tid >> 4;

    const float4* kp = (const float4*)(g_k + ((size_t)bh * TT + c * 64) * DH);
    const float4* vp = (const float4*)(g_v + ((size_t)bh * TT + c * 64) * DH);
    for (int i = tid; i < 1024; i += 256) {
        ((float4*)ks)[i] = kp[i];
        ((float4*)vs)[i] = vp[i];
    }
    __syncthreads();

    float acc[4][4] = {};
    #pragma unroll 8
    for (int t = 0; t < 64; t++) {
        float4 a = *(const float4*)&ks[t][ty * 4];
        float4 b = *(const float4*)&vs[t][tx * 4];
        acc[0][0] += a.x * b.x; acc[0][1] += a.x * b.y; acc[0][2] += a.x * b.z; acc[0][3] += a.x * b.w;
        acc[1][0] += a.y * b.x; acc[1][1] += a.y * b.y; acc[1][2] += a.y * b.z; acc[1][3] += a.y * b.w;
        acc[2][0] += a.z * b.x; acc[2][1] += a.z * b.y; acc[2][2] += a.z * b.z; acc[2][3] += a.z * b.w;
        acc[3][0] += a.w * b.x; acc[3][1] += a.w * b.y; acc[3][2] += a.w * b.z; acc[3][3] += a.w * b.w;
    }

    float* kvout = g_kv + ((size_t)bh * NC + c) * 4096;
    #pragma unroll
    for (int i = 0; i < 4; i++)
        *(float4*)&kvout[(ty * 4 + i) * 64 + tx * 4] =
            make_float4(acc[i][0], acc[i][1], acc[i][2], acc[i][3]);
    if (tid < 64) {
        float s = 0.f;
        #pragma unroll 8
        for (int t = 0; t < 64; t++) s += ks[t][tid];
        g_ks[((size_t)bh * NC + c) * 64 + tid] = s;
    }
}

// ---------------------------------------------------------------------------
// Exclusive prefix scan across chunks (per bh)
// ---------------------------------------------------------------------------
__global__ __launch_bounds__(256) void prefix_scan()
{
    const int bh = blockIdx.x;
    float* base = g_kv + (size_t)bh * NC * 4096;
    for (int p = threadIdx.x; p < 4096; p += 256) {
        float run = 0.f;
        #pragma unroll
        for (int c = 0; c < NC; c++) {
            float tmp = base[c * 4096 + p];
            base[c * 4096 + p] = run;
            run += tmp;
        }
    }
    if (threadIdx.x < 64) {
        float run = 0.f;
        float* kb = g_ks + (size_t)bh * NC * 64 + threadIdx.x;
        #pragma unroll
        for (int c = 0; c < NC; c++) {
            float tmp = kb[c * 64];
            kb[c * 64] = run;
            run += tmp;
        }
    }
}

// ---------------------------------------------------------------------------
// Per-chunk attention output
// ---------------------------------------------------------------------------
__global__ __launch_bounds__(256) void attn_chunk()
{
    __shared__ float Qs[64 * 64];
    __shared__ float KA[64 * 64];
    __shared__ float VS[64 * 64];

    const int c = blockIdx.x, bh = blockIdx.y;
    const int tid = threadIdx.x, tx = tid & 15, ty = tid >> 4;

    const float* qp = g_q + ((size_t)bh * TT + c * 64) * DH;
    const float* kp = g_k + ((size_t)bh * TT + c * 64) * DH;
    const float* vp = g_v + ((size_t)bh * TT + c * 64) * DH;

    for (int i = tid; i < 1024; i += 256) {
        ((float4*)Qs)[i] = ((const float4*)qp)[i];
        ((float4*)VS)[i] = ((const float4*)vp)[i];
        float4 kv4 = ((const float4*)kp)[i];
        const int r = i >> 4, d0 = (i & 15) << 2;
        KA[(d0 + 0) * 64 + r] = kv4.x;
        KA[(d0 + 1) * 64 + r] = kv4.y;
        KA[(d0 + 2) * 64 + r] = kv4.z;
        KA[(d0 + 3) * 64 + r] = kv4.w;
    }
    __syncthreads();

    float a[4][4] = {};
    #pragma unroll 8
    for (int d = 0; d < 64; d++) {
        float q0 = Qs[(ty * 4 + 0) * 64 + d];
        float q1 = Qs[(ty * 4 + 1) * 64 + d];
        float q2 = Qs[(ty * 4 + 2) * 64 + d];
        float q3 = Qs[(ty * 4 + 3) * 64 + d];
        float4 kc = *(const float4*)&KA[d * 64 + tx * 4];
        a[0][0] += q0 * kc.x; a[0][1] += q0 * kc.y; a[0][2] += q0 * kc.z; a[0][3] += q0 * kc.w;
        a[1][0] += q1 * kc.x; a[1][1] += q1 * kc.y; a[1][2] += q1 * kc.z; a[1][3] += q1 * kc.w;
        a[2][0] += q2 * kc.x; a[2][1] += q2 * kc.y; a[2][2] += q2 * kc.z; a[2][3] += q2 * kc.w;
        a[3][0] += q3 * kc.x; a[3][1] += q3 * kc.y; a[3][2] += q3 * kc.z; a[3][3] += q3 * kc.w;
    }
    #pragma unroll
    for (int i = 0; i < 4; i++)
        #pragma unroll
        for (int j = 0; j < 4; j++)
            if (tx * 4 + j > ty * 4 + i) a[i][j] = 0.f;

    float rsum[4];
    #pragma unroll
    for (int i = 0; i < 4; i++) {
        float s = a[i][0] + a[i][1] + a[i][2] + a[i][3];
        #pragma unroll
        for (int off = 1; off < 16; off <<= 1)
            s += __shfl_xor_sync(0xffffffffu, s, off);
        rsum[i] = s;
    }

    __syncthreads();
    #pragma unroll
    for (int i = 0; i < 4; i++)
        *(float4*)&KA[(ty * 4 + i) * 64 + tx * 4] =
            make_float4(a[i][0], a[i][1], a[i][2], a[i][3]);
    __syncthreads();

    float acc[4][4] = {};
    #pragma unroll 8
    for (int t = 0; t < 64; t++) {
        float a0 = KA[(ty * 4 + 0) * 64 + t];
        float a1 = KA[(ty * 4 + 1) * 64 + t];
        float a2 = KA[(ty * 4 + 2) * 64 + t];
        float a3 = KA[(ty * 4 + 3) * 64 + t];
        float4 vv = *(const float4*)&VS[t * 64 + tx * 4];
        acc[0][0] += a0 * vv.x; acc[0][1] += a0 * vv.y; acc[0][2] += a0 * vv.z; acc[0][3] += a0 * vv.w;
        acc[1][0] += a1 * vv.x; acc[1][1] += a1 * vv.y; acc[1][2] += a1 * vv.z; acc[1][3] += a1 * vv.w;
        acc[2][0] += a2 * vv.x; acc[2][1] += a2 * vv.y; acc[2][2] += a2 * vv.z; acc[2][3] += a2 * vv.w;
        acc[3][0] += a3 * vv.x; acc[3][1] += a3 * vv.y; acc[3][2] += a3 * vv.z; acc[3][3] += a3 * vv.w;
    }
    __syncthreads();

    const float4* sp = (const float4*)(g_kv + ((size_t)bh * NC + c) * 4096);
    for (int i = tid; i < 1024; i += 256) ((float4*)VS)[i] = sp[i];
    __syncthreads();

    const float* zp = g_ks + ((size_t)bh * NC + c) * 64;
    float qz[4] = {};
    #pragma unroll 8
    for (int d = 0; d < 64; d++) {
        float q0 = Qs[(ty * 4 + 0) * 64 + d];
        float q1 = Qs[(ty * 4 + 1) * 64 + d];
        float q2 = Qs[(ty * 4 + 2) * 64 + d];
        float q3 = Qs[(ty * 4 + 3) * 64 + d];
        float4 sv = *(const float4*)&VS[d * 64 + tx * 4];
        float z = zp[d];
        acc[0][0] += q0 * sv.x; acc[0][1] += q0 * sv.y; acc[0][2] += q0 * sv.z; acc[0][3] += q0 * sv.w;
        acc[1][0] += q1 * sv.x; acc[1][1] += q1 * sv.y; acc[1][2] += q1 * sv.z; acc[1][3] += q1 * sv.w;
        acc[2][0] += q2 * sv.x; acc[2][1] += q2 * sv.y; acc[2][2] += q2 * sv.z; acc[2][3] += q2 * sv.w;
        acc[3][0] += q3 * sv.x; acc[3][1] += q3 * sv.y; acc[3][2] += q3 * sv.z; acc[3][3] += q3 * sv.w;
        qz[0] += q0 * z; qz[1] += q1 * z; qz[2] += q2 * z; qz[3] += q3 * z;
    }

    const int b = bh >> 4, h = bh & 15;
    #pragma unroll
    for (int i = 0; i < 4; i++) {
        const float den = fmaxf(rsum[i] + qz[i], EPSF);
        const float inv = 1.0f / den;
        const int tg = c * 64 + ty * 4 + i;
        *(float4*)&g_att[((size_t)(b * TT + tg)) * DD + h * 64 + tx * 4] =
            make_float4(acc[i][0] * inv, acc[i][1] * inv, acc[i][2] * inv, acc[i][3] * inv);
    }
}

// ---------------------------------------------------------------------------
extern "C" void kernel_launch(void* const* d_in, const int* in_sizes, int n_in,
                              void* d_out, int out_size)
{
    const float* x  = (const float*)d_in[0];
    const float* Wq = (const float*)d_in[1];
    const float* bq = (const float*)d_in[2];
    const float* Wk = (const float*)d_in[3];
    const float* bk = (const float*)d_in[4];
    const float* Wv = (const float*)d_in[5];
    const float* bv = (const float*)d_in[6];
    const float* Wo = (const float*)d_in[7];
    const float* bo = (const float*)d_in[8];
    float* out = (float*)d_out;

    float *q, *k, *v, *att;
    cudaGetSymbolAddress((void**)&q,   g_q);
    cudaGetSymbolAddress((void**)&k,   g_k);
    cudaGetSymbolAddress((void**)&v,   g_v);
    cudaGetSymbolAddress((void**)&att, g_att);

    cudaFuncSetAttribute(mma_gemm, cudaFuncAttributeMaxDynamicSharedMemorySize, SMEM_DYN);

    // Fused Q/K/V projections (z selects matrix); Q,K get the feature map.
    mma_gemm<<<dim3(DD / BN, MM / BM, 3), 256, SMEM_DYN>>>(
        x, Wq, bq, q, 1, Wk, bk, k, 1, Wv, bv, v, 0, /*head_layout=*/1);

    chunk_kv<<<dim3(NC, BH), 256>>>();
    prefix_scan<<<BH, 256>>>();
    attn_chunk<<<dim3(NC, BH), 256>>>();

    // Output projection
    mma_gemm<<<dim3(DD / BN, MM / BM, 1), 256, SMEM_DYN>>>(
        att, Wo, bo, out, 0, Wo, bo, out, 0, Wo, bo, out, 0, /*head_layout=*/0);
}

// round 4
// speedup vs baseline: 2.0872x; 1.0147x over previous
#include <cuda_runtime.h>
#include <cuda_bf16.h>
#include <cstdint>

// Problem constants
#define BB   2
#define TT   2048
#define DD   1024
#define HH   16
#define DH   64
#define NC   32           // TT / 64 chunks
#define BH   32           // BB * HH
#define MM   4096         // BB * TT
#define EPSF 1e-6f

// GEMM tiling
#define BM   128
#define BN   128
#define BK   32
#define NKB  (DD / BK)    // 32 k-stages
#define ROWB  80          // padded row stride bytes (32 bf16 = 64B data + 16B pad)
#define TILEB (128 * ROWB)          // 10240 B per tile
#define STG   (4 * TILEB)           // Ahi | Alo | Bhi | Blo = 40960 B
#define NSTG  3
#define SMEM_DYN (NSTG * STG)       // 122880 B

// Scratch (device globals; allocation is forbidden)
__device__ float g_q[BH * TT * DH];        // [b,h,t,dh]
__device__ float g_k[BH * TT * DH];
__device__ float g_v[BH * TT * DH];
__device__ float g_kv[BH * NC * DH * DH];  // per-chunk KV, then exclusive prefix
__device__ float g_ks[BH * NC * DH];       // per-chunk k-sum, then exclusive prefix

// Persistent split-bf16 copies
__device__ __nv_bfloat16 g_xhi[MM * DD];
__device__ __nv_bfloat16 g_xlo[MM * DD];
__device__ __nv_bfloat16 g_whi[4 * DD * DD];   // Wq | Wk | Wv | Wo
__device__ __nv_bfloat16 g_wlo[4 * DD * DD];
__device__ __nv_bfloat16 g_ahi[MM * DD];       // attention output, split
__device__ __nv_bfloat16 g_alo[MM * DD];

// ---------------------------------------------------------------------------
// helpers
// ---------------------------------------------------------------------------
__device__ __forceinline__ uint32_t smem_u32(const void* p) {
    uint32_t a;
    asm("{ .reg .u64 t; cvta.to.shared.u64 t, %1; cvt.u32.u64 %0, t; }"
        : "=r"(a) : "l"(p));
    return a;
}
__device__ __forceinline__ uint32_t packbf2(__nv_bfloat16 lo, __nv_bfloat16 hi) {
    __nv_bfloat162 h = __halves2bfloat162(lo, hi);
    return *(uint32_t*)&h;
}
__device__ __forceinline__ void mma16816(float* c, const uint32_t* a, const uint32_t* b) {
    asm volatile(
        "mma.sync.aligned.m16n8k16.row.col.f32.bf16.bf16.f32 "
        "{%0,%1,%2,%3}, {%4,%5,%6,%7}, {%8,%9}, {%0,%1,%2,%3};"
        : "+f"(c[0]), "+f"(c[1]), "+f"(c[2]), "+f"(c[3])
        : "r"(a[0]), "r"(a[1]), "r"(a[2]), "r"(a[3]), "r"(b[0]), "r"(b[1]));
}
__device__ __forceinline__ void ldsm4(uint32_t* r, uint32_t addr) {
    asm volatile("ldmatrix.sync.aligned.m8n8.x4.shared.b16 {%0,%1,%2,%3}, [%4];"
                 : "=r"(r[0]), "=r"(r[1]), "=r"(r[2]), "=r"(r[3]) : "r"(addr));
}
__device__ __forceinline__ void cp16(uint32_t dst, const void* src) {
    asm volatile("cp.async.cg.shared.global [%0], [%1], 16;"
                 :: "r"(dst), "l"(src) : "memory");
}
#define CP_COMMIT() asm volatile("cp.async.commit_group;" ::: "memory")
#define CP_WAIT1()  asm volatile("cp.async.wait_group 1;"  ::: "memory")

// ---------------------------------------------------------------------------
// One-time fp32 -> (hi,lo) bf16 split
// ---------------------------------------------------------------------------
__global__ __launch_bounds__(256) void conv_split(
    const float* __restrict__ src, __nv_bfloat16* __restrict__ hi,
    __nv_bfloat16* __restrict__ lo, int n4)
{
    int i = blockIdx.x * 256 + threadIdx.x;
    if (i >= n4) return;
    float4 v = ((const float4*)src)[i];
    __nv_bfloat16 h0 = __float2bfloat16(v.x), h1 = __float2bfloat16(v.y);
    __nv_bfloat16 h2 = __float2bfloat16(v.z), h3 = __float2bfloat16(v.w);
    __nv_bfloat16 l0 = __float2bfloat16(v.x - __bfloat162float(h0));
    __nv_bfloat16 l1 = __float2bfloat16(v.y - __bfloat162float(h1));
    __nv_bfloat16 l2 = __float2bfloat16(v.z - __bfloat162float(h2));
    __nv_bfloat16 l3 = __float2bfloat16(v.w - __bfloat162float(h3));
    uint2 uh, ul;
    uh.x = packbf2(h0, h1); uh.y = packbf2(h2, h3);
    ul.x = packbf2(l0, l1); ul.y = packbf2(l2, l3);
    ((uint2*)hi)[i] = uh;
    ((uint2*)lo)[i] = ul;
}

// ---------------------------------------------------------------------------
// Split-bf16 tensor-core GEMM v2: pre-split bf16 inputs, cp.async 3-stage
// pipeline, ldmatrix fragments. out[m][n] = fm( sum_k A[m][k]*B[n][k] + bias )
// 128x128 CTA, BK=32, 8 warps, warp tile 64x32, 3 HMMA per frag pair (split).
// blockIdx.z selects weight set (QKV fusion).
// ---------------------------------------------------------------------------
__global__ __launch_bounds__(256, 1) void mma_gemm2(
    const __nv_bfloat16* __restrict__ Ahi, const __nv_bfloat16* __restrict__ Alo,
    const __nv_bfloat16* __restrict__ Whi, const __nv_bfloat16* __restrict__ Wlo,
    const float* __restrict__ bz0, const float* __restrict__ bz1, const float* __restrict__ bz2,
    float* __restrict__ o0, float* __restrict__ o1, float* __restrict__ o2,
    int f0, int f1, int f2, int head_layout)
{
    extern __shared__ char dsm[];

    const int z = blockIdx.z;
    const __nv_bfloat16* Bhi = Whi + (size_t)z * DD * DD;
    const __nv_bfloat16* Blo = Wlo + (size_t)z * DD * DD;
    const float* bias = (z == 0) ? bz0 : (z == 1) ? bz1 : bz2;
    float*       outp = (z == 0) ? o0  : (z == 1) ? o1  : o2;
    const int    fm   = (z == 0) ? f0  : (z == 1) ? f1  : f2;

    const int tid  = threadIdx.x;
    const int wid  = tid >> 5, lane = tid & 31;
    const int m0   = blockIdx.y * BM, n0 = blockIdx.x * BN;
    const int wm   = (wid >> 2) * 64, wn = (wid & 3) * 32;
    const int g    = lane >> 2, tig = lane & 3;
    const uint32_t sb = smem_u32(dsm);

    float acc[4][4][4];
    #pragma unroll
    for (int i = 0; i < 4; i++)
        #pragma unroll
        for (int j = 0; j < 4; j++)
            #pragma unroll
            for (int q = 0; q < 4; q++) acc[i][j][q] = 0.f;

    // staging coords: each thread moves 32B (two 16B chunks) per tile
    const int srow = tid >> 1;          // 0..127
    const int scol = (tid & 1) * 16;    // element col 0 or 16
    const uint32_t doff = (uint32_t)srow * ROWB + scol * 2;

    auto issue = [&](int c, int s) {
        const uint32_t base = sb + s * STG;
        const int kb = c * BK;
        const __nv_bfloat16* ah = Ahi + (size_t)(m0 + srow) * DD + kb + scol;
        const __nv_bfloat16* al = Alo + (size_t)(m0 + srow) * DD + kb + scol;
        const __nv_bfloat16* bh = Bhi + (size_t)(n0 + srow) * DD + kb + scol;
        const __nv_bfloat16* bl = Blo + (size_t)(n0 + srow) * DD + kb + scol;
        cp16(base + doff,                  ah);
        cp16(base + doff + 16,             ah + 8);
        cp16(base + TILEB + doff,          al);
        cp16(base + TILEB + doff + 16,     al + 8);
        cp16(base + 2 * TILEB + doff,      bh);
        cp16(base + 2 * TILEB + doff + 16, bh + 8);
        cp16(base + 3 * TILEB + doff,      bl);
        cp16(base + 3 * TILEB + doff + 16, bl + 8);
    };

    auto compute = [&](int s) {
        const uint32_t base = sb + s * STG;
        #pragma unroll
        for (int kt = 0; kt < 2; kt++) {
            const uint32_t kby = kt * 32;   // 16 bf16 = 32 bytes
            uint32_t bh[4][2], bl[4][2];
            #pragma unroll
            for (int ntp = 0; ntp < 2; ntp++) {
                const uint32_t baddr = base + 2 * TILEB +
                    (uint32_t)(wn + ntp * 16 + ((lane >> 4) & 1) * 8 + (lane & 7)) * ROWB +
                    kby + ((lane >> 3) & 1) * 16;
                uint32_t t[4];
                ldsm4(t, baddr);
                bh[2 * ntp][0] = t[0]; bh[2 * ntp][1] = t[1];
                bh[2 * ntp + 1][0] = t[2]; bh[2 * ntp + 1][1] = t[3];
                ldsm4(t, baddr + TILEB);
                bl[2 * ntp][0] = t[0]; bl[2 * ntp][1] = t[1];
                bl[2 * ntp + 1][0] = t[2]; bl[2 * ntp + 1][1] = t[3];
            }
            #pragma unroll
            for (int mt = 0; mt < 4; mt++) {
                const uint32_t aaddr = base +
                    (uint32_t)(wm + mt * 16 + ((lane >> 3) & 1) * 8 + (lane & 7)) * ROWB +
                    kby + ((lane >> 4) & 1) * 16;
                uint32_t ah[4], al[4];
                ldsm4(ah, aaddr);
                ldsm4(al, aaddr + TILEB);
                #pragma unroll
                for (int nt = 0; nt < 4; nt++) {
                    mma16816(acc[mt][nt], ah, bh[nt]);
                    mma16816(acc[mt][nt], ah, bl[nt]);
                    mma16816(acc[mt][nt], al, bh[nt]);
                }
            }
        }
    };

    issue(0, 0); CP_COMMIT();
    issue(1, 1); CP_COMMIT();

    for (int c = 0; c < NKB; c++) {
        CP_WAIT1();
        __syncthreads();
        compute(c % NSTG);
        if (c + 2 < NKB) issue(c + 2, (c + 2) % NSTG);
        CP_COMMIT();
    }

    // Epilogue: bias + optional ELU+1 feature map + store
    const int hcol = (n0 + wn) >> 6;
    #pragma unroll
    for (int mt = 0; mt < 4; mt++) {
        const int r0 = m0 + wm + mt * 16 + g;
        #pragma unroll
        for (int nt = 0; nt < 4; nt++) {
            const int cn = n0 + wn + nt * 8 + 2 * tig;
            float v0 = acc[mt][nt][0] + bias[cn];
            float v1 = acc[mt][nt][1] + bias[cn + 1];
            float v2 = acc[mt][nt][2] + bias[cn];
            float v3 = acc[mt][nt][3] + bias[cn + 1];
            if (fm) {
                v0 = (v0 > 0.f) ? (v0 + 1.f) : expf(v0);
                v1 = (v1 > 0.f) ? (v1 + 1.f) : expf(v1);
                v2 = (v2 > 0.f) ? (v2 + 1.f) : expf(v2);
                v3 = (v3 > 0.f) ? (v3 + 1.f) : expf(v3);
            }
            if (head_layout) {
                const int b = r0 >> 11, t = r0 & (TT - 1);
                const int dh = cn & 63;
                float* p = outp + ((size_t)((b * HH + hcol) * TT + t)) * DH + dh;
                *(float2*)p            = make_float2(v0, v1);
                *(float2*)(p + 8 * DH) = make_float2(v2, v3);
            } else {
                float* p = outp + (size_t)r0 * DD + cn;
                *(float2*)p            = make_float2(v0, v1);
                *(float2*)(p + 8 * DD) = make_float2(v2, v3);
            }
        }
    }
}

// ---------------------------------------------------------------------------
// Per-chunk stats: KV_c[d][e] = sum_t k[t][d] * v[t][e];  ksum_c[d] = sum_t k[t][d]
// ---------------------------------------------------------------------------
__global__ __launch_bounds__(256) void chunk_kv()
{
    __shared__ float ks[64][64];
    __shared__ float vs[64][64];
    const int c = blockIdx.x, bh = blockIdx.y;
    const int tid = threadIdx.x, tx = tid & 15, ty = tid >> 4;

    const float4* kp = (const float4*)(g_k + ((size_t)bh * TT + c * 64) * DH);
    const float4* vp = (const float4*)(g_v + ((size_t)bh * TT + c * 64) * DH);
    for (int i = tid; i < 1024; i += 256) {
        ((float4*)ks)[i] = kp[i];
        ((float4*)vs)[i] = vp[i];
    }
    __syncthreads();

    float acc[4][4] = {};
    #pragma unroll 8
    for (int t = 0; t < 64; t++) {
        float4 a = *(const float4*)&ks[t][ty * 4];
        float4 b = *(const float4*)&vs[t][tx * 4];
        acc[0][0] += a.x * b.x; acc[0][1] += a.x * b.y; acc[0][2] += a.x * b.z; acc[0][3] += a.x * b.w;
        acc[1][0] += a.y * b.x; acc[1][1] += a.y * b.y; acc[1][2] += a.y * b.z; acc[1][3] += a.y * b.w;
        acc[2][0] += a.z * b.x; acc[2][1] += a.z * b.y; acc[2][2] += a.z * b.z; acc[2][3] += a.z * b.w;
        acc[3][0] += a.w * b.x; acc[3][1] += a.w * b.y; acc[3][2] += a.w * b.z; acc[3][3] += a.w * b.w;
    }

    float* kvout = g_kv + ((size_t)bh * NC + c) * 4096;
    #pragma unroll
    for (int i = 0; i < 4; i++)
        *(float4*)&kvout[(ty * 4 + i) * 64 + tx * 4] =
            make_float4(acc[i][0], acc[i][1], acc[i][2], acc[i][3]);
    if (tid < 64) {
        float s = 0.f;
        #pragma unroll 8
        for (int t = 0; t < 64; t++) s += ks[t][tid];
        g_ks[((size_t)bh * NC + c) * 64 + tid] = s;
    }
}

// ---------------------------------------------------------------------------
// Exclusive prefix scan across chunks (per bh)
// ---------------------------------------------------------------------------
__global__ __launch_bounds__(256) void prefix_scan()
{
    const int bh = blockIdx.x;
    float* base = g_kv + (size_t)bh * NC * 4096;
    for (int p = threadIdx.x; p < 4096; p += 256) {
        float run = 0.f;
        #pragma unroll
        for (int c = 0; c < NC; c++) {
            float tmp = base[c * 4096 + p];
            base[c * 4096 + p] = run;
            run += tmp;
        }
    }
    if (threadIdx.x < 64) {
        float run = 0.f;
        float* kb = g_ks + (size_t)bh * NC * 64 + threadIdx.x;
        #pragma unroll
        for (int c = 0; c < NC; c++) {
            float tmp = kb[c * 64];
            kb[c * 64] = run;
            run += tmp;
        }
    }
}

// ---------------------------------------------------------------------------
// Per-chunk attention output; epilogue writes SPLIT bf16 (hi/lo) for O-gemm
// ---------------------------------------------------------------------------
__global__ __launch_bounds__(256) void attn_chunk()
{
    __shared__ float Qs[64 * 64];
    __shared__ float KA[64 * 64];
    __shared__ float VS[64 * 64];

    const int c = blockIdx.x, bh = blockIdx.y;
    const int tid = threadIdx.x, tx = tid & 15, ty = tid >> 4;

    const float* qp = g_q + ((size_t)bh * TT + c * 64) * DH;
    const float* kp = g_k + ((size_t)bh * TT + c * 64) * DH;
    const float* vp = g_v + ((size_t)bh * TT + c * 64) * DH;

    for (int i = tid; i < 1024; i += 256) {
        ((float4*)Qs)[i] = ((const float4*)qp)[i];
        ((float4*)VS)[i] = ((const float4*)vp)[i];
        float4 kv4 = ((const float4*)kp)[i];
        const int r = i >> 4, d0 = (i & 15) << 2;
        KA[(d0 + 0) * 64 + r] = kv4.x;
        KA[(d0 + 1) * 64 + r] = kv4.y;
        KA[(d0 + 2) * 64 + r] = kv4.z;
        KA[(d0 + 3) * 64 + r] = kv4.w;
    }
    __syncthreads();

    float a[4][4] = {};
    #pragma unroll 8
    for (int d = 0; d < 64; d++) {
        float q0 = Qs[(ty * 4 + 0) * 64 + d];
        float q1 = Qs[(ty * 4 + 1) * 64 + d];
        float q2 = Qs[(ty * 4 + 2) * 64 + d];
        float q3 = Qs[(ty * 4 + 3) * 64 + d];
        float4 kc = *(const float4*)&KA[d * 64 + tx * 4];
        a[0][0] += q0 * kc.x; a[0][1] += q0 * kc.y; a[0][2] += q0 * kc.z; a[0][3] += q0 * kc.w;
        a[1][0] += q1 * kc.x; a[1][1] += q1 * kc.y; a[1][2] += q1 * kc.z; a[1][3] += q1 * kc.w;
        a[2][0] += q2 * kc.x; a[2][1] += q2 * kc.y; a[2][2] += q2 * kc.z; a[2][3] += q2 * kc.w;
        a[3][0] += q3 * kc.x; a[3][1] += q3 * kc.y; a[3][2] += q3 * kc.z; a[3][3] += q3 * kc.w;
    }
    #pragma unroll
    for (int i = 0; i < 4; i++)
        #pragma unroll
        for (int j = 0; j < 4; j++)
            if (tx * 4 + j > ty * 4 + i) a[i][j] = 0.f;

    float rsum[4];
    #pragma unroll
    for (int i = 0; i < 4; i++) {
        float s = a[i][0] + a[i][1] + a[i][2] + a[i][3];
        #pragma unroll
        for (int off = 1; off < 16; off <<= 1)
            s += __shfl_xor_sync(0xffffffffu, s, off);
        rsum[i] = s;
    }

    __syncthreads();
    #pragma unroll
    for (int i = 0; i < 4; i++)
        *(float4*)&KA[(ty * 4 + i) * 64 + tx * 4] =
            make_float4(a[i][0], a[i][1], a[i][2], a[i][3]);
    __syncthreads();

    float acc[4][4] = {};
    #pragma unroll 8
    for (int t = 0; t < 64; t++) {
        float a0 = KA[(ty * 4 + 0) * 64 + t];
        float a1 = KA[(ty * 4 + 1) * 64 + t];
        float a2 = KA[(ty * 4 + 2) * 64 + t];
        float a3 = KA[(ty * 4 + 3) * 64 + t];
        float4 vv = *(const float4*)&VS[t * 64 + tx * 4];
        acc[0][0] += a0 * vv.x; acc[0][1] += a0 * vv.y; acc[0][2] += a0 * vv.z; acc[0][3] += a0 * vv.w;
        acc[1][0] += a1 * vv.x; acc[1][1] += a1 * vv.y; acc[1][2] += a1 * vv.z; acc[1][3] += a1 * vv.w;
        acc[2][0] += a2 * vv.x; acc[2][1] += a2 * vv.y; acc[2][2] += a2 * vv.z; acc[2][3] += a2 * vv.w;
        acc[3][0] += a3 * vv.x; acc[3][1] += a3 * vv.y; acc[3][2] += a3 * vv.z; acc[3][3] += a3 * vv.w;
    }
    __syncthreads();

    const float4* sp = (const float4*)(g_kv + ((size_t)bh * NC + c) * 4096);
    for (int i = tid; i < 1024; i += 256) ((float4*)VS)[i] = sp[i];
    __syncthreads();

    const float* zp = g_ks + ((size_t)bh * NC + c) * 64;
    float qz[4] = {};
    #pragma unroll 8
    for (int d = 0; d < 64; d++) {
        float q0 = Qs[(ty * 4 + 0) * 64 + d];
        float q1 = Qs[(ty * 4 + 1) * 64 + d];
        float q2 = Qs[(ty * 4 + 2) * 64 + d];
        float q3 = Qs[(ty * 4 + 3) * 64 + d];
        float4 sv = *(const float4*)&VS[d * 64 + tx * 4];
        float z = zp[d];
        acc[0][0] += q0 * sv.x; acc[0][1] += q0 * sv.y; acc[0][2] += q0 * sv.z; acc[0][3] += q0 * sv.w;
        acc[1][0] += q1 * sv.x; acc[1][1] += q1 * sv.y; acc[1][2] += q1 * sv.z; acc[1][3] += q1 * sv.w;
        acc[2][0] += q2 * sv.x; acc[2][1] += q2 * sv.y; acc[2][2] += q2 * sv.z; acc[2][3] += q2 * sv.w;
        acc[3][0] += q3 * sv.x; acc[3][1] += q3 * sv.y; acc[3][2] += q3 * sv.z; acc[3][3] += q3 * sv.w;
        qz[0] += q0 * z; qz[1] += q1 * z; qz[2] += q2 * z; qz[3] += q3 * z;
    }

    const int b = bh >> 4, h = bh & 15;
    #pragma unroll
    for (int i = 0; i < 4; i++) {
        const float den = fmaxf(rsum[i] + qz[i], EPSF);
        const float inv = 1.0f / den;
        const int tg = c * 64 + ty * 4 + i;
        float o0 = acc[i][0] * inv, o1 = acc[i][1] * inv;
        float o2 = acc[i][2] * inv, o3 = acc[i][3] * inv;
        __nv_bfloat16 h0 = __float2bfloat16(o0), h1 = __float2bfloat16(o1);
        __nv_bfloat16 h2 = __float2bfloat16(o2), h3 = __float2bfloat16(o3);
        __nv_bfloat16 l0 = __float2bfloat16(o0 - __bfloat162float(h0));
        __nv_bfloat16 l1 = __float2bfloat16(o1 - __bfloat162float(h1));
        __nv_bfloat16 l2 = __float2bfloat16(o2 - __bfloat162float(h2));
        __nv_bfloat16 l3 = __float2bfloat16(o3 - __bfloat162float(h3));
        const size_t idx = ((size_t)(b * TT + tg)) * DD + h * 64 + tx * 4;
        uint2 uh, ul;
        uh.x = packbf2(h0, h1); uh.y = packbf2(h2, h3);
        ul.x = packbf2(l0, l1); ul.y = packbf2(l2, l3);
        *(uint2*)(g_ahi + idx) = uh;
        *(uint2*)(g_alo + idx) = ul;
    }
}

// ---------------------------------------------------------------------------
extern "C" void kernel_launch(void* const* d_in, const int* in_sizes, int n_in,
                              void* d_out, int out_size)
{
    const float* x  = (const float*)d_in[0];
    const float* Wq = (const float*)d_in[1];
    const float* bq = (const float*)d_in[2];
    const float* Wk = (const float*)d_in[3];
    const float* bk = (const float*)d_in[4];
    const float* Wv = (const float*)d_in[5];
    const float* bv = (const float*)d_in[6];
    const float* Wo = (const float*)d_in[7];
    const float* bo = (const float*)d_in[8];
    float* out = (float*)d_out;

    float *q, *k, *v;
    __nv_bfloat16 *xhi, *xlo, *whi, *wlo, *ahi, *alo;
    cudaGetSymbolAddress((void**)&q,   g_q);
    cudaGetSymbolAddress((void**)&k,   g_k);
    cudaGetSymbolAddress((void**)&v,   g_v);
    cudaGetSymbolAddress((void**)&xhi, g_xhi);
    cudaGetSymbolAddress((void**)&xlo, g_xlo);
    cudaGetSymbolAddress((void**)&whi, g_whi);
    cudaGetSymbolAddress((void**)&wlo, g_wlo);
    cudaGetSymbolAddress((void**)&ahi, g_ahi);
    cudaGetSymbolAddress((void**)&alo, g_alo);

    cudaFuncSetAttribute(mma_gemm2, cudaFuncAttributeMaxDynamicSharedMemorySize, SMEM_DYN);

    // One-time splits
    conv_split<<<(MM * DD / 4) / 256, 256>>>(x, xhi, xlo, MM * DD / 4);
    conv_split<<<(DD * DD / 4) / 256, 256>>>(Wq, whi + 0 * DD * DD, wlo + 0 * DD * DD, DD * DD / 4);
    conv_split<<<(DD * DD / 4) / 256, 256>>>(Wk, whi + 1 * DD * DD, wlo + 1 * DD * DD, DD * DD / 4);
    conv_split<<<(DD * DD / 4) / 256, 256>>>(Wv, whi + 2 * DD * DD, wlo + 2 * DD * DD, DD * DD / 4);
    conv_split<<<(DD * DD / 4) / 256, 256>>>(Wo, whi + 3 * DD * DD, wlo + 3 * DD * DD, DD * DD / 4);

    // Fused Q/K/V projections (z selects matrix); Q,K get the feature map.
    mma_gemm2<<<dim3(DD / BN, MM / BM, 3), 256, SMEM_DYN>>>(
        xhi, xlo, whi, wlo, bq, bk, bv, q, k, v, 1, 1, 0, /*head_layout=*/1);

    chunk_kv<<<dim3(NC, BH), 256>>>();
    prefix_scan<<<BH, 256>>>();
    attn_chunk<<<dim3(NC, BH), 256>>>();

    // Output projection (A = attention output, W = Wo at offset 3)
    mma_gemm2<<<dim3(DD / BN, MM / BM, 1), 256, SMEM_DYN>>>(
        ahi, alo, whi + 3 * DD * DD, wlo + 3 * DD * DD, bo, bo, bo,
        out, out, out, 0, 0, 0, /*head_layout=*/0);
}

// round 5
// speedup vs baseline: 2.9007x; 1.3897x over previous
#include <cuda_runtime.h>
#include <cuda_fp16.h>
#include <cstdint>

// Problem constants
#define BB   2
#define TT   2048
#define DD   1024
#define HH   16
#define DH   64
#define NC   32           // TT / 64 chunks
#define BH   32           // BB * HH
#define MM   4096         // BB * TT
#define EPSF 1e-6f

// GEMM tiling
#define BM   128
#define BN   128
#define BK   32
#define NKB  (DD / BK)    // 32 k-stages
#define ROWB  80          // padded row stride bytes (32 fp16 = 64B data + 16B pad)
#define TILEB (128 * ROWB)          // 10240 B per tile
#define STG   (3 * TILEB)           // Ahi | Alo | Bhi = 30720 B
#define NSTG  3
#define SMEM_DYN (NSTG * STG)       // 92160 B

// Scratch (device globals; allocation is forbidden)
__device__ float g_q[BH * TT * DH];        // [b,h,t,dh]
__device__ float g_k[BH * TT * DH];
__device__ float g_v[BH * TT * DH];
__device__ float g_kv[BH * NC * DH * DH];  // per-chunk KV, then exclusive prefix
__device__ float g_ks[BH * NC * DH];       // per-chunk k-sum, then exclusive prefix

// Persistent fp16 copies (A side split hi/lo; W side hi only)
__device__ __half g_xhi[MM * DD];
__device__ __half g_xlo[MM * DD];
__device__ __half g_whi[4 * DD * DD];      // Wq | Wk | Wv | Wo
__device__ __half g_ahi[MM * DD];          // attention output, split
__device__ __half g_alo[MM * DD];

// ---------------------------------------------------------------------------
// helpers
// ---------------------------------------------------------------------------
__device__ __forceinline__ uint32_t smem_u32(const void* p) {
    uint32_t a;
    asm("{ .reg .u64 t; cvta.to.shared.u64 t, %1; cvt.u32.u64 %0, t; }"
        : "=r"(a) : "l"(p));
    return a;
}
__device__ __forceinline__ uint32_t packh2(__half lo, __half hi) {
    __half2 h = __halves2half2(lo, hi);
    return *(uint32_t*)&h;
}
__device__ __forceinline__ void mma16816(float* c, const uint32_t* a, const uint32_t* b) {
    asm volatile(
        "mma.sync.aligned.m16n8k16.row.col.f32.f16.f16.f32 "
        "{%0,%1,%2,%3}, {%4,%5,%6,%7}, {%8,%9}, {%0,%1,%2,%3};"
        : "+f"(c[0]), "+f"(c[1]), "+f"(c[2]), "+f"(c[3])
        : "r"(a[0]), "r"(a[1]), "r"(a[2]), "r"(a[3]), "r"(b[0]), "r"(b[1]));
}
__device__ __forceinline__ void ldsm4(uint32_t* r, uint32_t addr) {
    asm volatile("ldmatrix.sync.aligned.m8n8.x4.shared.b16 {%0,%1,%2,%3}, [%4];"
                 : "=r"(r[0]), "=r"(r[1]), "=r"(r[2]), "=r"(r[3]) : "r"(addr));
}
__device__ __forceinline__ void cp16(uint32_t dst, const void* src) {
    asm volatile("cp.async.cg.shared.global [%0], [%1], 16;"
                 :: "r"(dst), "l"(src) : "memory");
}
#define CP_COMMIT() asm volatile("cp.async.commit_group;" ::: "memory")
#define CP_WAIT1()  asm volatile("cp.async.wait_group 1;"  ::: "memory")

// ---------------------------------------------------------------------------
// One-time fp32 -> (hi,lo) fp16 split
// ---------------------------------------------------------------------------
__global__ __launch_bounds__(256) void conv_split_h(
    const float* __restrict__ src, __half* __restrict__ hi,
    __half* __restrict__ lo, int n4)
{
    int i = blockIdx.x * 256 + threadIdx.x;
    if (i >= n4) return;
    float4 v = ((const float4*)src)[i];
    __half h0 = __float2half(v.x), h1 = __float2half(v.y);
    __half h2 = __float2half(v.z), h3 = __float2half(v.w);
    __half l0 = __float2half(v.x - __half2float(h0));
    __half l1 = __float2half(v.y - __half2float(h1));
    __half l2 = __float2half(v.z - __half2float(h2));
    __half l3 = __float2half(v.w - __half2float(h3));
    uint2 uh, ul;
    uh.x = packh2(h0, h1); uh.y = packh2(h2, h3);
    ul.x = packh2(l0, l1); ul.y = packh2(l2, l3);
    ((uint2*)hi)[i] = uh;
    ((uint2*)lo)[i] = ul;
}

// One-time fp32 -> fp16 cast (weights)
__global__ __launch_bounds__(256) void conv_cast_h(
    const float* __restrict__ src, __half* __restrict__ hi, int n4)
{
    int i = blockIdx.x * 256 + threadIdx.x;
    if (i >= n4) return;
    float4 v = ((const float4*)src)[i];
    uint2 uh;
    uh.x = packh2(__float2half(v.x), __float2half(v.y));
    uh.y = packh2(__float2half(v.z), __float2half(v.w));
    ((uint2*)hi)[i] = uh;
}

// ---------------------------------------------------------------------------
// Split-fp16 tensor-core GEMM: out[m][n] = fm( sum_k A[m][k]*B[n][k] + bias )
// A = Ahi + Alo (fp16 pair), B = Bhi (fp16). 2 HMMA per fragment pair.
// 128x128 CTA, BK=32, 8 warps, warp tile 64x32, cp.async 3-stage, ldmatrix.
// blockIdx.z selects weight set (QKV fusion).
// ---------------------------------------------------------------------------
__global__ __launch_bounds__(256) void mma_gemm3(
    const __half* __restrict__ Ahi, const __half* __restrict__ Alo,
    const __half* __restrict__ Whi,
    const float* __restrict__ bz0, const float* __restrict__ bz1, const float* __restrict__ bz2,
    float* __restrict__ o0, float* __restrict__ o1, float* __restrict__ o2,
    int f0, int f1, int f2, int head_layout)
{
    extern __shared__ char dsm[];

    const int z = blockIdx.z;
    const __half* Bhi = Whi + (size_t)z * DD * DD;
    const float* bias = (z == 0) ? bz0 : (z == 1) ? bz1 : bz2;
    float*       outp = (z == 0) ? o0  : (z == 1) ? o1  : o2;
    const int    fm   = (z == 0) ? f0  : (z == 1) ? f1  : f2;

    const int tid  = threadIdx.x;
    const int wid  = tid >> 5, lane = tid & 31;
    const int m0   = blockIdx.y * BM, n0 = blockIdx.x * BN;
    const int wm   = (wid >> 2) * 64, wn = (wid & 3) * 32;
    const int g    = lane >> 2, tig = lane & 3;
    const uint32_t sb = smem_u32(dsm);

    float acc[4][4][4];
    #pragma unroll
    for (int i = 0; i < 4; i++)
        #pragma unroll
        for (int j = 0; j < 4; j++)
            #pragma unroll
            for (int q = 0; q < 4; q++) acc[i][j][q] = 0.f;

    // staging coords: each thread moves 2x16B per tile
    const int srow = tid >> 1;          // 0..127
    const int scol = (tid & 1) * 16;    // element col 0 or 16
    const uint32_t doff = (uint32_t)srow * ROWB + scol * 2;

    auto issue = [&](int c, int s) {
        const uint32_t base = sb + s * STG;
        const int kb = c * BK;
        const __half* ah = Ahi + (size_t)(m0 + srow) * DD + kb + scol;
        const __half* al = Alo + (size_t)(m0 + srow) * DD + kb + scol;
        const __half* bh = Bhi + (size_t)(n0 + srow) * DD + kb + scol;
        cp16(base + doff,                  ah);
        cp16(base + doff + 16,             ah + 8);
        cp16(base + TILEB + doff,          al);
        cp16(base + TILEB + doff + 16,     al + 8);
        cp16(base + 2 * TILEB + doff,      bh);
        cp16(base + 2 * TILEB + doff + 16, bh + 8);
    };

    auto compute = [&](int s) {
        const uint32_t base = sb + s * STG;
        #pragma unroll
        for (int kt = 0; kt < 2; kt++) {
            const uint32_t kby = kt * 32;   // 16 fp16 = 32 bytes
            uint32_t bh[4][2];
            #pragma unroll
            for (int ntp = 0; ntp < 2; ntp++) {
                const uint32_t baddr = base + 2 * TILEB +
                    (uint32_t)(wn + ntp * 16 + ((lane >> 4) & 1) * 8 + (lane & 7)) * ROWB +
                    kby + ((lane >> 3) & 1) * 16;
                uint32_t t[4];
                ldsm4(t, baddr);
                bh[2 * ntp][0] = t[0];     bh[2 * ntp][1] = t[1];
                bh[2 * ntp + 1][0] = t[2]; bh[2 * ntp + 1][1] = t[3];
            }
            #pragma unroll
            for (int mt = 0; mt < 4; mt++) {
                const uint32_t aaddr = base +
                    (uint32_t)(wm + mt * 16 + ((lane >> 3) & 1) * 8 + (lane & 7)) * ROWB +
                    kby + ((lane >> 4) & 1) * 16;
                uint32_t ah[4], al[4];
                ldsm4(ah, aaddr);
                ldsm4(al, aaddr + TILEB);
                #pragma unroll
                for (int nt = 0; nt < 4; nt++) {
                    mma16816(acc[mt][nt], ah, bh[nt]);
                    mma16816(acc[mt][nt], al, bh[nt]);
                }
            }
        }
    };

    issue(0, 0); CP_COMMIT();
    issue(1, 1); CP_COMMIT();

    for (int c = 0; c < NKB; c++) {
        CP_WAIT1();
        __syncthreads();
        compute(c % NSTG);
        if (c + 2 < NKB) issue(c + 2, (c + 2) % NSTG);
        CP_COMMIT();
    }

    // Epilogue: bias + optional ELU+1 feature map + store
    const int hcol = (n0 + wn) >> 6;
    #pragma unroll
    for (int mt = 0; mt < 4; mt++) {
        const int r0 = m0 + wm + mt * 16 + g;
        #pragma unroll
        for (int nt = 0; nt < 4; nt++) {
            const int cn = n0 + wn + nt * 8 + 2 * tig;
            float v0 = acc[mt][nt][0] + bias[cn];
            float v1 = acc[mt][nt][1] + bias[cn + 1];
            float v2 = acc[mt][nt][2] + bias[cn];
            float v3 = acc[mt][nt][3] + bias[cn + 1];
            if (fm) {
                v0 = (v0 > 0.f) ? (v0 + 1.f) : expf(v0);
                v1 = (v1 > 0.f) ? (v1 + 1.f) : expf(v1);
                v2 = (v2 > 0.f) ? (v2 + 1.f) : expf(v2);
                v3 = (v3 > 0.f) ? (v3 + 1.f) : expf(v3);
            }
            if (head_layout) {
                const int b = r0 >> 11, t = r0 & (TT - 1);
                const int dh = cn & 63;
                float* p = outp + ((size_t)((b * HH + hcol) * TT + t)) * DH + dh;
                *(float2*)p            = make_float2(v0, v1);
                *(float2*)(p + 8 * DH) = make_float2(v2, v3);
            } else {
                float* p = outp + (size_t)r0 * DD + cn;
                *(float2*)p            = make_float2(v0, v1);
                *(float2*)(p + 8 * DD) = make_float2(v2, v3);
            }
        }
    }
}

// ---------------------------------------------------------------------------
// Per-chunk stats: KV_c[d][e] = sum_t k[t][d] * v[t][e];  ksum_c[d] = sum_t k[t][d]
// ---------------------------------------------------------------------------
__global__ __launch_bounds__(256) void chunk_kv()
{
    __shared__ float ks[64][64];
    __shared__ float vs[64][64];
    const int c = blockIdx.x, bh = blockIdx.y;
    const int tid = threadIdx.x, tx = tid & 15, ty = tid >> 4;

    const float4* kp = (const float4*)(g_k + ((size_t)bh * TT + c * 64) * DH);
    const float4* vp = (const float4*)(g_v + ((size_t)bh * TT + c * 64) * DH);
    for (int i = tid; i < 1024; i += 256) {
        ((float4*)ks)[i] = kp[i];
        ((float4*)vs)[i] = vp[i];
    }
    __syncthreads();

    float acc[4][4] = {};
    #pragma unroll 8
    for (int t = 0; t < 64; t++) {
        float4 a = *(const float4*)&ks[t][ty * 4];
        float4 b = *(const float4*)&vs[t][tx * 4];
        acc[0][0] += a.x * b.x; acc[0][1] += a.x * b.y; acc[0][2] += a.x * b.z; acc[0][3] += a.x * b.w;
        acc[1][0] += a.y * b.x; acc[1][1] += a.y * b.y; acc[1][2] += a.y * b.z; acc[1][3] += a.y * b.w;
        acc[2][0] += a.z * b.x; acc[2][1] += a.z * b.y; acc[2][2] += a.z * b.z; acc[2][3] += a.z * b.w;
        acc[3][0] += a.w * b.x; acc[3][1] += a.w * b.y; acc[3][2] += a.w * b.z; acc[3][3] += a.w * b.w;
    }

    float* kvout = g_kv + ((size_t)bh * NC + c) * 4096;
    #pragma unroll
    for (int i = 0; i < 4; i++)
        *(float4*)&kvout[(ty * 4 + i) * 64 + tx * 4] =
            make_float4(acc[i][0], acc[i][1], acc[i][2], acc[i][3]);
    if (tid < 64) {
        float s = 0.f;
        #pragma unroll 8
        for (int t = 0; t < 64; t++) s += ks[t][tid];
        g_ks[((size_t)bh * NC + c) * 64 + tid] = s;
    }
}

// ---------------------------------------------------------------------------
// Exclusive prefix scan across chunks (per bh)
// ---------------------------------------------------------------------------
__global__ __launch_bounds__(256) void prefix_scan()
{
    const int bh = blockIdx.x;
    float* base = g_kv + (size_t)bh * NC * 4096;
    for (int p = threadIdx.x; p < 4096; p += 256) {
        float run = 0.f;
        #pragma unroll
        for (int c = 0; c < NC; c++) {
            float tmp = base[c * 4096 + p];
            base[c * 4096 + p] = run;
            run += tmp;
        }
    }
    if (threadIdx.x < 64) {
        float run = 0.f;
        float* kb = g_ks + (size_t)bh * NC * 64 + threadIdx.x;
        #pragma unroll
        for (int c = 0; c < NC; c++) {
            float tmp = kb[c * 64];
            kb[c * 64] = run;
            run += tmp;
        }
    }
}

// ---------------------------------------------------------------------------
// Per-chunk attention output; epilogue writes SPLIT fp16 (hi/lo) for O-gemm
// ---------------------------------------------------------------------------
__global__ __launch_bounds__(256) void attn_chunk()
{
    __shared__ float Qs[64 * 64];
    __shared__ float KA[64 * 64];
    __shared__ float VS[64 * 64];

    const int c = blockIdx.x, bh = blockIdx.y;
    const int tid = threadIdx.x, tx = tid & 15, ty = tid >> 4;

    const float* qp = g_q + ((size_t)bh * TT + c * 64) * DH;
    const float* kp = g_k + ((size_t)bh * TT + c * 64) * DH;
    const float* vp = g_v + ((size_t)bh * TT + c * 64) * DH;

    for (int i = tid; i < 1024; i += 256) {
        ((float4*)Qs)[i] = ((const float4*)qp)[i];
        ((float4*)VS)[i] = ((const float4*)vp)[i];
        float4 kv4 = ((const float4*)kp)[i];
        const int r = i >> 4, d0 = (i & 15) << 2;
        KA[(d0 + 0) * 64 + r] = kv4.x;
        KA[(d0 + 1) * 64 + r] = kv4.y;
        KA[(d0 + 2) * 64 + r] = kv4.z;
        KA[(d0 + 3) * 64 + r] = kv4.w;
    }
    __syncthreads();

    float a[4][4] = {};
    #pragma unroll 8
    for (int d = 0; d < 64; d++) {
        float q0 = Qs[(ty * 4 + 0) * 64 + d];
        float q1 = Qs[(ty * 4 + 1) * 64 + d];
        float q2 = Qs[(ty * 4 + 2) * 64 + d];
        float q3 = Qs[(ty * 4 + 3) * 64 + d];
        float4 kc = *(const float4*)&KA[d * 64 + tx * 4];
        a[0][0] += q0 * kc.x; a[0][1] += q0 * kc.y; a[0][2] += q0 * kc.z; a[0][3] += q0 * kc.w;
        a[1][0] += q1 * kc.x; a[1][1] += q1 * kc.y; a[1][2] += q1 * kc.z; a[1][3] += q1 * kc.w;
        a[2][0] += q2 * kc.x; a[2][1] += q2 * kc.y; a[2][2] += q2 * kc.z; a[2][3] += q2 * kc.w;
        a[3][0] += q3 * kc.x; a[3][1] += q3 * kc.y; a[3][2] += q3 * kc.z; a[3][3] += q3 * kc.w;
    }
    #pragma unroll
    for (int i = 0; i < 4; i++)
        #pragma unroll
        for (int j = 0; j < 4; j++)
            if (tx * 4 + j > ty * 4 + i) a[i][j] = 0.f;

    float rsum[4];
    #pragma unroll
    for (int i = 0; i < 4; i++) {
        float s = a[i][0] + a[i][1] + a[i][2] + a[i][3];
        #pragma unroll
        for (int off = 1; off < 16; off <<= 1)
            s += __shfl_xor_sync(0xffffffffu, s, off);
        rsum[i] = s;
    }

    __syncthreads();
    #pragma unroll
    for (int i = 0; i < 4; i++)
        *(float4*)&KA[(ty * 4 + i) * 64 + tx * 4] =
            make_float4(a[i][0], a[i][1], a[i][2], a[i][3]);
    __syncthreads();

    float acc[4][4] = {};
    #pragma unroll 8
    for (int t = 0; t < 64; t++) {
        float a0 = KA[(ty * 4 + 0) * 64 + t];
        float a1 = KA[(ty * 4 + 1) * 64 + t];
        float a2 = KA[(ty * 4 + 2) * 64 + t];
        float a3 = KA[(ty * 4 + 3) * 64 + t];
        float4 vv = *(const float4*)&VS[t * 64 + tx * 4];
        acc[0][0] += a0 * vv.x; acc[0][1] += a0 * vv.y; acc[0][2] += a0 * vv.z; acc[0][3] += a0 * vv.w;
        acc[1][0] += a1 * vv.x; acc[1][1] += a1 * vv.y; acc[1][2] += a1 * vv.z; acc[1][3] += a1 * vv.w;
        acc[2][0] += a2 * vv.x; acc[2][1] += a2 * vv.y; acc[2][2] += a2 * vv.z; acc[2][3] += a2 * vv.w;
        acc[3][0] += a3 * vv.x; acc[3][1] += a3 * vv.y; acc[3][2] += a3 * vv.z; acc[3][3] += a3 * vv.w;
    }
    __syncthreads();

    const float4* sp = (const float4*)(g_kv + ((size_t)bh * NC + c) * 4096);
    for (int i = tid; i < 1024; i += 256) ((float4*)VS)[i] = sp[i];
    __syncthreads();

    const float* zp = g_ks + ((size_t)bh * NC + c) * 64;
    float qz[4] = {};
    #pragma unroll 8
    for (int d = 0; d < 64; d++) {
        float q0 = Qs[(ty * 4 + 0) * 64 + d];
        float q1 = Qs[(ty * 4 + 1) * 64 + d];
        float q2 = Qs[(ty * 4 + 2) * 64 + d];
        float q3 = Qs[(ty * 4 + 3) * 64 + d];
        float4 sv = *(const float4*)&VS[d * 64 + tx * 4];
        float z = zp[d];
        acc[0][0] += q0 * sv.x; acc[0][1] += q0 * sv.y; acc[0][2] += q0 * sv.z; acc[0][3] += q0 * sv.w;
        acc[1][0] += q1 * sv.x; acc[1][1] += q1 * sv.y; acc[1][2] += q1 * sv.z; acc[1][3] += q1 * sv.w;
        acc[2][0] += q2 * sv.x; acc[2][1] += q2 * sv.y; acc[2][2] += q2 * sv.z; acc[2][3] += q2 * sv.w;
        acc[3][0] += q3 * sv.x; acc[3][1] += q3 * sv.y; acc[3][2] += q3 * sv.z; acc[3][3] += q3 * sv.w;
        qz[0] += q0 * z; qz[1] += q1 * z; qz[2] += q2 * z; qz[3] += q3 * z;
    }

    const int b = bh >> 4, h = bh & 15;
    #pragma unroll
    for (int i = 0; i < 4; i++) {
        const float den = fmaxf(rsum[i] + qz[i], EPSF);
        const float inv = 1.0f / den;
        const int tg = c * 64 + ty * 4 + i;
        float o0 = acc[i][0] * inv, o1 = acc[i][1] * inv;
        float o2 = acc[i][2] * inv, o3 = acc[i][3] * inv;
        __half h0 = __float2half(o0), h1 = __float2half(o1);
        __half h2 = __float2half(o2), h3 = __float2half(o3);
        __half l0 = __float2half(o0 - __half2float(h0));
        __half l1 = __float2half(o1 - __half2float(h1));
        __half l2 = __float2half(o2 - __half2float(h2));
        __half l3 = __float2half(o3 - __half2float(h3));
        const size_t idx = ((size_t)(b * TT + tg)) * DD + h * 64 + tx * 4;
        uint2 uh, ul;
        uh.x = packh2(h0, h1); uh.y = packh2(h2, h3);
        ul.x = packh2(l0, l1); ul.y = packh2(l2, l3);
        *(uint2*)(g_ahi + idx) = uh;
        *(uint2*)(g_alo + idx) = ul;
    }
}

// ---------------------------------------------------------------------------
extern "C" void kernel_launch(void* const* d_in, const int* in_sizes, int n_in,
                              void* d_out, int out_size)
{
    const float* x  = (const float*)d_in[0];
    const float* Wq = (const float*)d_in[1];
    const float* bq = (const float*)d_in[2];
    const float* Wk = (const float*)d_in[3];
    const float* bk = (const float*)d_in[4];
    const float* Wv = (const float*)d_in[5];
    const float* bv = (const float*)d_in[6];
    const float* Wo = (const float*)d_in[7];
    const float* bo = (const float*)d_in[8];
    float* out = (float*)d_out;

    float *q, *k, *v;
    __half *xhi, *xlo, *whi, *ahi, *alo;
    cudaGetSymbolAddress((void**)&q,   g_q);
    cudaGetSymbolAddress((void**)&k,   g_k);
    cudaGetSymbolAddress((void**)&v,   g_v);
    cudaGetSymbolAddress((void**)&xhi, g_xhi);
    cudaGetSymbolAddress((void**)&xlo, g_xlo);
    cudaGetSymbolAddress((void**)&whi, g_whi);
    cudaGetSymbolAddress((void**)&ahi, g_ahi);
    cudaGetSymbolAddress((void**)&alo, g_alo);

    cudaFuncSetAttribute(mma_gemm3, cudaFuncAttributeMaxDynamicSharedMemorySize, SMEM_DYN);

    // One-time conversions
    conv_split_h<<<(MM * DD / 4) / 256, 256>>>(x, xhi, xlo, MM * DD / 4);
    conv_cast_h<<<(DD * DD / 4) / 256, 256>>>(Wq, whi + 0 * (size_t)DD * DD, DD * DD / 4);
    conv_cast_h<<<(DD * DD / 4) / 256, 256>>>(Wk, whi + 1 * (size_t)DD * DD, DD * DD / 4);
    conv_cast_h<<<(DD * DD / 4) / 256, 256>>>(Wv, whi + 2 * (size_t)DD * DD, DD * DD / 4);
    conv_cast_h<<<(DD * DD / 4) / 256, 256>>>(Wo, whi + 3 * (size_t)DD * DD, DD * DD / 4);

    // Fused Q/K/V projections (z selects matrix); Q,K get the feature map.
    mma_gemm3<<<dim3(DD / BN, MM / BM, 3), 256, SMEM_DYN>>>(
        xhi, xlo, whi, bq, bk, bv, q, k, v, 1, 1, 0, /*head_layout=*/1);

    chunk_kv<<<dim3(NC, BH), 256>>>();
    prefix_scan<<<BH, 256>>>();
    attn_chunk<<<dim3(NC, BH), 256>>>();

    // Output projection (A = attention output, W = Wo at offset 3)
    mma_gemm3<<<dim3(DD / BN, MM / BM, 1), 256, SMEM_DYN>>>(
        ahi, alo, whi + 3 * (size_t)DD * DD, bo, bo, bo,
        out, out, out, 0, 0, 0, /*head_layout=*/0);
}

// round 6
// speedup vs baseline: 4.3731x; 1.5076x over previous
#include <cuda_runtime.h>
#include <cuda_fp16.h>
#include <cstdint>

// Problem constants
#define BB   2
#define TT   2048
#define DD   1024
#define HH   16
#define DH   64
#define NC   32           // TT / 64 chunks
#define BH   32           // BB * HH
#define MM   4096         // BB * TT
#define EPSF 1e-6f

// GEMM tiling
#define BM   128
#define BN   128
#define BK   32
#define NKB  (DD / BK)    // 32 k-stages
#define ROWB  80          // padded row stride bytes (32 fp16 = 64B data + 16B pad)
#define TILEB (128 * ROWB)          // 10240 B per tile
#define STG   (2 * TILEB)           // A | B = 20480 B
#define NSTG  3
#define SMEM_DYN (NSTG * STG)       // 61440 B

#define XN4 (MM * DD / 4)
#define WN4 (DD * DD / 4)

// Scratch (device globals; allocation is forbidden)
__device__ float g_q[BH * TT * DH];        // [b,h,t,dh]
__device__ float g_k[BH * TT * DH];
__device__ float g_v[BH * TT * DH];
__device__ float g_kv[BH * NC * DH * DH];  // per-chunk KV, then exclusive prefix
__device__ float g_ks[BH * NC * DH];       // per-chunk k-sum, then exclusive prefix

// Persistent fp16 copies
__device__ __half g_xh[MM * DD];
__device__ __half g_wh[4 * DD * DD];       // Wq | Wk | Wv | Wo
__device__ __half g_ah[MM * DD];           // attention output

// ---------------------------------------------------------------------------
// helpers
// ---------------------------------------------------------------------------
__device__ __forceinline__ uint32_t smem_u32(const void* p) {
    uint32_t a;
    asm("{ .reg .u64 t; cvta.to.shared.u64 t, %1; cvt.u32.u64 %0, t; }"
        : "=r"(a) : "l"(p));
    return a;
}
__device__ __forceinline__ uint32_t packh2(__half lo, __half hi) {
    __half2 h = __halves2half2(lo, hi);
    return *(uint32_t*)&h;
}
__device__ __forceinline__ void mma16816(float* c, const uint32_t* a, const uint32_t* b) {
    asm volatile(
        "mma.sync.aligned.m16n8k16.row.col.f32.f16.f16.f32 "
        "{%0,%1,%2,%3}, {%4,%5,%6,%7}, {%8,%9}, {%0,%1,%2,%3};"
        : "+f"(c[0]), "+f"(c[1]), "+f"(c[2]), "+f"(c[3])
        : "r"(a[0]), "r"(a[1]), "r"(a[2]), "r"(a[3]), "r"(b[0]), "r"(b[1]));
}
__device__ __forceinline__ void ldsm4(uint32_t* r, uint32_t addr) {
    asm volatile("ldmatrix.sync.aligned.m8n8.x4.shared.b16 {%0,%1,%2,%3}, [%4];"
                 : "=r"(r[0]), "=r"(r[1]), "=r"(r[2]), "=r"(r[3]) : "r"(addr));
}
__device__ __forceinline__ void cp16(uint32_t dst, const void* src) {
    asm volatile("cp.async.cg.shared.global [%0], [%1], 16;"
                 :: "r"(dst), "l"(src) : "memory");
}
#define CP_COMMIT() asm volatile("cp.async.commit_group;" ::: "memory")
#define CP_WAIT1()  asm volatile("cp.async.wait_group 1;"  ::: "memory")

// ---------------------------------------------------------------------------
// Fused one-time fp32 -> fp16 cast: x (XN4 float4) then Wq/Wk/Wv/Wo
// ---------------------------------------------------------------------------
__global__ __launch_bounds__(256) void conv_all(
    const float* __restrict__ x,
    const float* __restrict__ Wq, const float* __restrict__ Wk,
    const float* __restrict__ Wv, const float* __restrict__ Wo)
{
    const int i = blockIdx.x * 256 + threadIdx.x;
    const float* src;
    __half* dst;
    int j;
    if (i < XN4) {
        src = x; dst = g_xh; j = i;
    } else {
        const int t = i - XN4;
        const int w = t / WN4;
        j = t - w * WN4;
        src = (w == 0) ? Wq : (w == 1) ? Wk : (w == 2) ? Wv : Wo;
        dst = g_wh + (size_t)w * DD * DD;
    }
    float4 v = ((const float4*)src)[j];
    uint2 u;
    u.x = packh2(__float2half(v.x), __float2half(v.y));
    u.y = packh2(__float2half(v.z), __float2half(v.w));
    ((uint2*)dst)[j] = u;
}

// ---------------------------------------------------------------------------
// fp16 tensor-core GEMM: out[m][n] = fm( sum_k A[m][k]*B[n][k] + bias[n] )
// 128x128 CTA, BK=32, 8 warps, warp tile 64x32, cp.async 3-stage, ldmatrix.
// fp32 accumulate. blockIdx.z selects weight set (QKV fusion).
// ---------------------------------------------------------------------------
__global__ __launch_bounds__(256) void mma_gemm4(
    const __half* __restrict__ A, const __half* __restrict__ W,
    const float* __restrict__ bz0, const float* __restrict__ bz1, const float* __restrict__ bz2,
    float* __restrict__ o0, float* __restrict__ o1, float* __restrict__ o2,
    int f0, int f1, int f2, int head_layout)
{
    extern __shared__ char dsm[];

    const int z = blockIdx.z;
    const __half* B = W + (size_t)z * DD * DD;
    const float* bias = (z == 0) ? bz0 : (z == 1) ? bz1 : bz2;
    float*       outp = (z == 0) ? o0  : (z == 1) ? o1  : o2;
    const int    fm   = (z == 0) ? f0  : (z == 1) ? f1  : f2;

    const int tid  = threadIdx.x;
    const int wid  = tid >> 5, lane = tid & 31;
    const int m0   = blockIdx.y * BM, n0 = blockIdx.x * BN;
    const int wm   = (wid >> 2) * 64, wn = (wid & 3) * 32;
    const int g    = lane >> 2, tig = lane & 3;
    const uint32_t sb = smem_u32(dsm);

    float acc[4][4][4];
    #pragma unroll
    for (int i = 0; i < 4; i++)
        #pragma unroll
        for (int j = 0; j < 4; j++)
            #pragma unroll
            for (int q = 0; q < 4; q++) acc[i][j][q] = 0.f;

    // staging coords: each thread moves 2x16B per tile
    const int srow = tid >> 1;          // 0..127
    const int scol = (tid & 1) * 16;    // element col 0 or 16
    const uint32_t doff = (uint32_t)srow * ROWB + scol * 2;

    auto issue = [&](int c, int s) {
        const uint32_t base = sb + s * STG;
        const int kb = c * BK;
        const __half* ap = A + (size_t)(m0 + srow) * DD + kb + scol;
        const __half* bp = B + (size_t)(n0 + srow) * DD + kb + scol;
        cp16(base + doff,              ap);
        cp16(base + doff + 16,         ap + 8);
        cp16(base + TILEB + doff,      bp);
        cp16(base + TILEB + doff + 16, bp + 8);
    };

    auto compute = [&](int s) {
        const uint32_t base = sb + s * STG;
        #pragma unroll
        for (int kt = 0; kt < 2; kt++) {
            const uint32_t kby = kt * 32;   // 16 fp16 = 32 bytes
            uint32_t bf[4][2];
            #pragma unroll
            for (int ntp = 0; ntp < 2; ntp++) {
                const uint32_t baddr = base + TILEB +
                    (uint32_t)(wn + ntp * 16 + ((lane >> 4) & 1) * 8 + (lane & 7)) * ROWB +
                    kby + ((lane >> 3) & 1) * 16;
                uint32_t t[4];
                ldsm4(t, baddr);
                bf[2 * ntp][0] = t[0];     bf[2 * ntp][1] = t[1];
                bf[2 * ntp + 1][0] = t[2]; bf[2 * ntp + 1][1] = t[3];
            }
            #pragma unroll
            for (int mt = 0; mt < 4; mt++) {
                const uint32_t aaddr = base +
                    (uint32_t)(wm + mt * 16 + ((lane >> 3) & 1) * 8 + (lane & 7)) * ROWB +
                    kby + ((lane >> 4) & 1) * 16;
                uint32_t af[4];
                ldsm4(af, aaddr);
                #pragma unroll
                for (int nt = 0; nt < 4; nt++)
                    mma16816(acc[mt][nt], af, bf[nt]);
            }
        }
    };

    issue(0, 0); CP_COMMIT();
    issue(1, 1); CP_COMMIT();

    for (int c = 0; c < NKB; c++) {
        CP_WAIT1();
        __syncthreads();
        compute(c % NSTG);
        if (c + 2 < NKB) issue(c + 2, (c + 2) % NSTG);
        CP_COMMIT();
    }

    // Epilogue: bias + optional ELU+1 feature map + store
    const int hcol = (n0 + wn) >> 6;
    #pragma unroll
    for (int mt = 0; mt < 4; mt++) {
        const int r0 = m0 + wm + mt * 16 + g;
        #pragma unroll
        for (int nt = 0; nt < 4; nt++) {
            const int cn = n0 + wn + nt * 8 + 2 * tig;
            float v0 = acc[mt][nt][0] + bias[cn];
            float v1 = acc[mt][nt][1] + bias[cn + 1];
            float v2 = acc[mt][nt][2] + bias[cn];
            float v3 = acc[mt][nt][3] + bias[cn + 1];
            if (fm) {
                v0 = (v0 > 0.f) ? (v0 + 1.f) : expf(v0);
                v1 = (v1 > 0.f) ? (v1 + 1.f) : expf(v1);
                v2 = (v2 > 0.f) ? (v2 + 1.f) : expf(v2);
                v3 = (v3 > 0.f) ? (v3 + 1.f) : expf(v3);
            }
            if (head_layout) {
                const int b = r0 >> 11, t = r0 & (TT - 1);
                const int dh = cn & 63;
                float* p = outp + ((size_t)((b * HH + hcol) * TT + t)) * DH + dh;
                *(float2*)p            = make_float2(v0, v1);
                *(float2*)(p + 8 * DH) = make_float2(v2, v3);
            } else {
                float* p = outp + (size_t)r0 * DD + cn;
                *(float2*)p            = make_float2(v0, v1);
                *(float2*)(p + 8 * DD) = make_float2(v2, v3);
            }
        }
    }
}

// ---------------------------------------------------------------------------
// Per-chunk stats: KV_c[d][e] = sum_t k[t][d] * v[t][e];  ksum_c[d] = sum_t k[t][d]
// ---------------------------------------------------------------------------
__global__ __launch_bounds__(256) void chunk_kv()
{
    __shared__ float ks[64][64];
    __shared__ float vs[64][64];
    const int c = blockIdx.x, bh = blockIdx.y;
    const int tid = threadIdx.x, tx = tid & 15, ty = tid >> 4;

    const float4* kp = (const float4*)(g_k + ((size_t)bh * TT + c * 64) * DH);
    const float4* vp = (const float4*)(g_v + ((size_t)bh * TT + c * 64) * DH);
    for (int i = tid; i < 1024; i += 256) {
        ((float4*)ks)[i] = kp[i];
        ((float4*)vs)[i] = vp[i];
    }
    __syncthreads();

    float acc[4][4] = {};
    #pragma unroll 8
    for (int t = 0; t < 64; t++) {
        float4 a = *(const float4*)&ks[t][ty * 4];
        float4 b = *(const float4*)&vs[t][tx * 4];
        acc[0][0] += a.x * b.x; acc[0][1] += a.x * b.y; acc[0][2] += a.x * b.z; acc[0][3] += a.x * b.w;
        acc[1][0] += a.y * b.x; acc[1][1] += a.y * b.y; acc[1][2] += a.y * b.z; acc[1][3] += a.y * b.w;
        acc[2][0] += a.z * b.x; acc[2][1] += a.z * b.y; acc[2][2] += a.z * b.z; acc[2][3] += a.z * b.w;
        acc[3][0] += a.w * b.x; acc[3][1] += a.w * b.y; acc[3][2] += a.w * b.z; acc[3][3] += a.w * b.w;
    }

    float* kvout = g_kv + ((size_t)bh * NC + c) * 4096;
    #pragma unroll
    for (int i = 0; i < 4; i++)
        *(float4*)&kvout[(ty * 4 + i) * 64 + tx * 4] =
            make_float4(acc[i][0], acc[i][1], acc[i][2], acc[i][3]);
    if (tid < 64) {
        float s = 0.f;
        #pragma unroll 8
        for (int t = 0; t < 64; t++) s += ks[t][tid];
        g_ks[((size_t)bh * NC + c) * 64 + tid] = s;
    }
}

// ---------------------------------------------------------------------------
// Exclusive prefix scan across chunks (per bh); grid (16, BH), 1 pos/thread
// ---------------------------------------------------------------------------
__global__ __launch_bounds__(256) void prefix_scan()
{
    const int bh = blockIdx.y;
    const int p = blockIdx.x * 256 + threadIdx.x;   // 0..4095
    float* base = g_kv + (size_t)bh * NC * 4096 + p;
    float run = 0.f;
    #pragma unroll
    for (int c = 0; c < NC; c++) {
        float tmp = base[c * 4096];
        base[c * 4096] = run;
        run += tmp;
    }
    if (blockIdx.x == 0 && threadIdx.x < 64) {
        float r2 = 0.f;
        float* kb = g_ks + (size_t)bh * NC * 64 + threadIdx.x;
        #pragma unroll
        for (int c = 0; c < NC; c++) {
            float tmp = kb[c * 64];
            kb[c * 64] = r2;
            r2 += tmp;
        }
    }
}

// ---------------------------------------------------------------------------
// Per-chunk attention output; epilogue writes fp16 for the O-gemm
// ---------------------------------------------------------------------------
__global__ __launch_bounds__(256) void attn_chunk()
{
    __shared__ float Qs[64 * 64];
    __shared__ float KA[64 * 64];
    __shared__ float VS[64 * 64];

    const int c = blockIdx.x, bh = blockIdx.y;
    const int tid = threadIdx.x, tx = tid & 15, ty = tid >> 4;

    const float* qp = g_q + ((size_t)bh * TT + c * 64) * DH;
    const float* kp = g_k + ((size_t)bh * TT + c * 64) * DH;
    const float* vp = g_v + ((size_t)bh * TT + c * 64) * DH;

    for (int i = tid; i < 1024; i += 256) {
        ((float4*)Qs)[i] = ((const float4*)qp)[i];
        ((float4*)VS)[i] = ((const float4*)vp)[i];
        float4 kv4 = ((const float4*)kp)[i];
        const int r = i >> 4, d0 = (i & 15) << 2;
        KA[(d0 + 0) * 64 + r] = kv4.x;
        KA[(d0 + 1) * 64 + r] = kv4.y;
        KA[(d0 + 2) * 64 + r] = kv4.z;
        KA[(d0 + 3) * 64 + r] = kv4.w;
    }
    __syncthreads();

    float a[4][4] = {};
    #pragma unroll 8
    for (int d = 0; d < 64; d++) {
        float q0 = Qs[(ty * 4 + 0) * 64 + d];
        float q1 = Qs[(ty * 4 + 1) * 64 + d];
        float q2 = Qs[(ty * 4 + 2) * 64 + d];
        float q3 = Qs[(ty * 4 + 3) * 64 + d];
        float4 kc = *(const float4*)&KA[d * 64 + tx * 4];
        a[0][0] += q0 * kc.x; a[0][1] += q0 * kc.y; a[0][2] += q0 * kc.z; a[0][3] += q0 * kc.w;
        a[1][0] += q1 * kc.x; a[1][1] += q1 * kc.y; a[1][2] += q1 * kc.z; a[1][3] += q1 * kc.w;
        a[2][0] += q2 * kc.x; a[2][1] += q2 * kc.y; a[2][2] += q2 * kc.z; a[2][3] += q2 * kc.w;
        a[3][0] += q3 * kc.x; a[3][1] += q3 * kc.y; a[3][2] += q3 * kc.z; a[3][3] += q3 * kc.w;
    }
    #pragma unroll
    for (int i = 0; i < 4; i++)
        #pragma unroll
        for (int j = 0; j < 4; j++)
            if (tx * 4 + j > ty * 4 + i) a[i][j] = 0.f;

    float rsum[4];
    #pragma unroll
    for (int i = 0; i < 4; i++) {
        float s = a[i][0] + a[i][1] + a[i][2] + a[i][3];
        #pragma unroll
        for (int off = 1; off < 16; off <<= 1)
            s += __shfl_xor_sync(0xffffffffu, s, off);
        rsum[i] = s;
    }

    __syncthreads();
    #pragma unroll
    for (int i = 0; i < 4; i++)
        *(float4*)&KA[(ty * 4 + i) * 64 + tx * 4] =
            make_float4(a[i][0], a[i][1], a[i][2], a[i][3]);
    __syncthreads();

    float acc[4][4] = {};
    #pragma unroll 8
    for (int t = 0; t < 64; t++) {
        float a0 = KA[(ty * 4 + 0) * 64 + t];
        float a1 = KA[(ty * 4 + 1) * 64 + t];
        float a2 = KA[(ty * 4 + 2) * 64 + t];
        float a3 = KA[(ty * 4 + 3) * 64 + t];
        float4 vv = *(const float4*)&VS[t * 64 + tx * 4];
        acc[0][0] += a0 * vv.x; acc[0][1] += a0 * vv.y; acc[0][2] += a0 * vv.z; acc[0][3] += a0 * vv.w;
        acc[1][0] += a1 * vv.x; acc[1][1] += a1 * vv.y; acc[1][2] += a1 * vv.z; acc[1][3] += a1 * vv.w;
        acc[2][0] += a2 * vv.x; acc[2][1] += a2 * vv.y; acc[2][2] += a2 * vv.z; acc[2][3] += a2 * vv.w;
        acc[3][0] += a3 * vv.x; acc[3][1] += a3 * vv.y; acc[3][2] += a3 * vv.z; acc[3][3] += a3 * vv.w;
    }
    __syncthreads();

    const float4* sp = (const float4*)(g_kv + ((size_t)bh * NC + c) * 4096);
    for (int i = tid; i < 1024; i += 256) ((float4*)VS)[i] = sp[i];
    __syncthreads();

    const float* zp = g_ks + ((size_t)bh * NC + c) * 64;
    float qz[4] = {};
    #pragma unroll 8
    for (int d = 0; d < 64; d++) {
        float q0 = Qs[(ty * 4 + 0) * 64 + d];
        float q1 = Qs[(ty * 4 + 1) * 64 + d];
        float q2 = Qs[(ty * 4 + 2) * 64 + d];
        float q3 = Qs[(ty * 4 + 3) * 64 + d];
        float4 sv = *(const float4*)&VS[d * 64 + tx * 4];
        float z = zp[d];
        acc[0][0] += q0 * sv.x; acc[0][1] += q0 * sv.y; acc[0][2] += q0 * sv.z; acc[0][3] += q0 * sv.w;
        acc[1][0] += q1 * sv.x; acc[1][1] += q1 * sv.y; acc[1][2] += q1 * sv.z; acc[1][3] += q1 * sv.w;
        acc[2][0] += q2 * sv.x; acc[2][1] += q2 * sv.y; acc[2][2] += q2 * sv.z; acc[2][3] += q2 * sv.w;
        acc[3][0] += q3 * sv.x; acc[3][1] += q3 * sv.y; acc[3][2] += q3 * sv.z; acc[3][3] += q3 * sv.w;
        qz[0] += q0 * z; qz[1] += q1 * z; qz[2] += q2 * z; qz[3] += q3 * z;
    }

    const int b = bh >> 4, h = bh & 15;
    #pragma unroll
    for (int i = 0; i < 4; i++) {
        const float den = fmaxf(rsum[i] + qz[i], EPSF);
        const float inv = 1.0f / den;
        const int tg = c * 64 + ty * 4 + i;
        const size_t idx = ((size_t)(b * TT + tg)) * DD + h * 64 + tx * 4;
        uint2 uh;
        uh.x = packh2(__float2half(acc[i][0] * inv), __float2half(acc[i][1] * inv));
        uh.y = packh2(__float2half(acc[i][2] * inv), __float2half(acc[i][3] * inv));
        *(uint2*)(g_ah + idx) = uh;
    }
}

// ---------------------------------------------------------------------------
extern "C" void kernel_launch(void* const* d_in, const int* in_sizes, int n_in,
                              void* d_out, int out_size)
{
    const float* x  = (const float*)d_in[0];
    const float* Wq = (const float*)d_in[1];
    const float* bq = (const float*)d_in[2];
    const float* Wk = (const float*)d_in[3];
    const float* bk = (const float*)d_in[4];
    const float* Wv = (const float*)d_in[5];
    const float* bv = (const float*)d_in[6];
    const float* Wo = (const float*)d_in[7];
    const float* bo = (const float*)d_in[8];
    float* out = (float*)d_out;

    float *q, *k, *v;
    __half *xh, *wh, *ah;
    cudaGetSymbolAddress((void**)&q,  g_q);
    cudaGetSymbolAddress((void**)&k,  g_k);
    cudaGetSymbolAddress((void**)&v,  g_v);
    cudaGetSymbolAddress((void**)&xh, g_xh);
    cudaGetSymbolAddress((void**)&wh, g_wh);
    cudaGetSymbolAddress((void**)&ah, g_ah);

    cudaFuncSetAttribute(mma_gemm4, cudaFuncAttributeMaxDynamicSharedMemorySize, SMEM_DYN);

    // Fused one-time conversion (x + all four weight matrices)
    conv_all<<<(XN4 + 4 * WN4) / 256, 256>>>(x, Wq, Wk, Wv, Wo);

    // Fused Q/K/V projections (z selects matrix); Q,K get the feature map.
    mma_gemm4<<<dim3(DD / BN, MM / BM, 3), 256, SMEM_DYN>>>(
        xh, wh, bq, bk, bv, q, k, v, 1, 1, 0, /*head_layout=*/1);

    chunk_kv<<<dim3(NC, BH), 256>>>();
    prefix_scan<<<dim3(16, BH), 256>>>();
    attn_chunk<<<dim3(NC, BH), 256>>>();

    // Output projection (A = attention output, W = Wo at offset 3)
    mma_gemm4<<<dim3(DD / BN, MM / BM, 1), 256, SMEM_DYN>>>(
        ah, wh + 3 * (size_t)DD * DD, bo, bo, bo,
        out, out, out, 0, 0, 0, /*head_layout=*/0);
}

// round 7
// speedup vs baseline: 5.3728x; 1.2286x over previous
#include <cuda_runtime.h>
#include <cuda_fp16.h>
#include <cstdint>

// Problem constants
#define BB   2
#define TT   2048
#define DD   1024
#define HH   16
#define DH   64
#define NC   32           // TT / 64 chunks
#define BH   32           // BB * HH
#define MM   4096         // BB * TT
#define EPSF 1e-6f

// GEMM tiling
#define BM   128
#define BN   128
#define BK   32
#define NKB  (DD / BK)    // 32 k-stages
#define ROWB  80          // padded row stride bytes (32 fp16 + 16B pad)
#define TILEB (128 * ROWB)
#define STG   (2 * TILEB)
#define NSTG  3
#define SMEM_DYN (NSTG * STG)

#define XN4 (MM * DD / 4)
#define WN4 (DD * DD / 4)

// attention smem row stride: 72 fp16 = 144B (conflict-free LDSM)
#define SR 72

// Scratch (device globals; allocation is forbidden)
__device__ __half g_q[BH * TT * DH];       // [b,h,t,dh] fp16
__device__ __half g_k[BH * TT * DH];
__device__ __half g_v[BH * TT * DH];
__device__ float  g_kv[BH * NC * DH * DH]; // per-chunk KV (fp32)
__device__ __half g_sh[BH * NC * DH * DH]; // exclusive-prefix S (fp16)
__device__ float  g_ks[BH * NC * DH];      // k-sum, then exclusive prefix (fp32)

// Persistent fp16 copies
__device__ __half g_xh[MM * DD];
__device__ __half g_wh[4 * DD * DD];       // Wq | Wk | Wv | Wo
__device__ __half g_ah[MM * DD];           // attention output

// ---------------------------------------------------------------------------
// helpers
// ---------------------------------------------------------------------------
__device__ __forceinline__ uint32_t smem_u32(const void* p) {
    uint32_t a;
    asm("{ .reg .u64 t; cvta.to.shared.u64 t, %1; cvt.u32.u64 %0, t; }"
        : "=r"(a) : "l"(p));
    return a;
}
__device__ __forceinline__ uint32_t packh2(__half lo, __half hi) {
    __half2 h = __halves2half2(lo, hi);
    return *(uint32_t*)&h;
}
__device__ __forceinline__ void mma16816(float* c, const uint32_t* a, const uint32_t* b) {
    asm volatile(
        "mma.sync.aligned.m16n8k16.row.col.f32.f16.f16.f32 "
        "{%0,%1,%2,%3}, {%4,%5,%6,%7}, {%8,%9}, {%0,%1,%2,%3};"
        : "+f"(c[0]), "+f"(c[1]), "+f"(c[2]), "+f"(c[3])
        : "r"(a[0]), "r"(a[1]), "r"(a[2]), "r"(a[3]), "r"(b[0]), "r"(b[1]));
}
__device__ __forceinline__ void ldsm4(uint32_t* r, uint32_t addr) {
    asm volatile("ldmatrix.sync.aligned.m8n8.x4.shared.b16 {%0,%1,%2,%3}, [%4];"
                 : "=r"(r[0]), "=r"(r[1]), "=r"(r[2]), "=r"(r[3]) : "r"(addr));
}
__device__ __forceinline__ void ldsm4t(uint32_t* r, uint32_t addr) {
    asm volatile("ldmatrix.sync.aligned.m8n8.x4.trans.shared.b16 {%0,%1,%2,%3}, [%4];"
                 : "=r"(r[0]), "=r"(r[1]), "=r"(r[2]), "=r"(r[3]) : "r"(addr));
}
__device__ __forceinline__ void cp16(uint32_t dst, const void* src) {
    asm volatile("cp.async.cg.shared.global [%0], [%1], 16;"
                 :: "r"(dst), "l"(src) : "memory");
}
#define CP_COMMIT() asm volatile("cp.async.commit_group;" ::: "memory")
#define CP_WAIT1()  asm volatile("cp.async.wait_group 1;"  ::: "memory")

// ---------------------------------------------------------------------------
// Fused one-time fp32 -> fp16 cast: x then Wq/Wk/Wv/Wo
// ---------------------------------------------------------------------------
__global__ __launch_bounds__(256) void conv_all(
    const float* __restrict__ x,
    const float* __restrict__ Wq, const float* __restrict__ Wk,
    const float* __restrict__ Wv, const float* __restrict__ Wo)
{
    const int i = blockIdx.x * 256 + threadIdx.x;
    const float* src;
    __half* dst;
    int j;
    if (i < XN4) {
        src = x; dst = g_xh; j = i;
    } else {
        const int t = i - XN4;
        const int w = t / WN4;
        j = t - w * WN4;
        src = (w == 0) ? Wq : (w == 1) ? Wk : (w == 2) ? Wv : Wo;
        dst = g_wh + (size_t)w * DD * DD;
    }
    float4 v = ((const float4*)src)[j];
    uint2 u;
    u.x = packh2(__float2half(v.x), __float2half(v.y));
    u.y = packh2(__float2half(v.z), __float2half(v.w));
    ((uint2*)dst)[j] = u;
}

// ---------------------------------------------------------------------------
// fp16 tensor-core GEMM. head_layout: write fp16 to hq/hk/hv in [b,h,t,dh];
// else write fp32 to o0 in [m][n].
// ---------------------------------------------------------------------------
__global__ __launch_bounds__(256) void mma_gemm4(
    const __half* __restrict__ A, const __half* __restrict__ W,
    const float* __restrict__ bz0, const float* __restrict__ bz1, const float* __restrict__ bz2,
    float* __restrict__ o0,
    __half* __restrict__ h0, __half* __restrict__ h1, __half* __restrict__ h2,
    int f0, int f1, int f2, int head_layout)
{
    extern __shared__ char dsm[];

    const int z = blockIdx.z;
    const __half* B = W + (size_t)z * DD * DD;
    const float* bias = (z == 0) ? bz0 : (z == 1) ? bz1 : bz2;
    __half*      houtp = (z == 0) ? h0 : (z == 1) ? h1 : h2;
    const int    fm   = (z == 0) ? f0  : (z == 1) ? f1  : f2;

    const int tid  = threadIdx.x;
    const int wid  = tid >> 5, lane = tid & 31;
    const int m0   = blockIdx.y * BM, n0 = blockIdx.x * BN;
    const int wm   = (wid >> 2) * 64, wn = (wid & 3) * 32;
    const int g    = lane >> 2, tig = lane & 3;
    const uint32_t sb = smem_u32(dsm);

    float acc[4][4][4];
    #pragma unroll
    for (int i = 0; i < 4; i++)
        #pragma unroll
        for (int j = 0; j < 4; j++)
            #pragma unroll
            for (int q = 0; q < 4; q++) acc[i][j][q] = 0.f;

    const int srow = tid >> 1;
    const int scol = (tid & 1) * 16;
    const uint32_t doff = (uint32_t)srow * ROWB + scol * 2;

    auto issue = [&](int c, int s) {
        const uint32_t base = sb + s * STG;
        const int kb = c * BK;
        const __half* ap = A + (size_t)(m0 + srow) * DD + kb + scol;
        const __half* bp = B + (size_t)(n0 + srow) * DD + kb + scol;
        cp16(base + doff,              ap);
        cp16(base + doff + 16,         ap + 8);
        cp16(base + TILEB + doff,      bp);
        cp16(base + TILEB + doff + 16, bp + 8);
    };

    auto compute = [&](int s) {
        const uint32_t base = sb + s * STG;
        #pragma unroll
        for (int kt = 0; kt < 2; kt++) {
            const uint32_t kby = kt * 32;
            uint32_t bf[4][2];
            #pragma unroll
            for (int ntp = 0; ntp < 2; ntp++) {
                const uint32_t baddr = base + TILEB +
                    (uint32_t)(wn + ntp * 16 + ((lane >> 4) & 1) * 8 + (lane & 7)) * ROWB +
                    kby + ((lane >> 3) & 1) * 16;
                uint32_t t[4];
                ldsm4(t, baddr);
                bf[2 * ntp][0] = t[0];     bf[2 * ntp][1] = t[1];
                bf[2 * ntp + 1][0] = t[2]; bf[2 * ntp + 1][1] = t[3];
            }
            #pragma unroll
            for (int mt = 0; mt < 4; mt++) {
                const uint32_t aaddr = base +
                    (uint32_t)(wm + mt * 16 + ((lane >> 3) & 1) * 8 + (lane & 7)) * ROWB +
                    kby + ((lane >> 4) & 1) * 16;
                uint32_t af[4];
                ldsm4(af, aaddr);
                #pragma unroll
                for (int nt = 0; nt < 4; nt++)
                    mma16816(acc[mt][nt], af, bf[nt]);
            }
        }
    };

    issue(0, 0); CP_COMMIT();
    issue(1, 1); CP_COMMIT();

    for (int c = 0; c < NKB; c++) {
        CP_WAIT1();
        __syncthreads();
        compute(c % NSTG);
        if (c + 2 < NKB) issue(c + 2, (c + 2) % NSTG);
        CP_COMMIT();
    }

    const int hcol = (n0 + wn) >> 6;
    #pragma unroll
    for (int mt = 0; mt < 4; mt++) {
        const int r0 = m0 + wm + mt * 16 + g;
        #pragma unroll
        for (int nt = 0; nt < 4; nt++) {
            const int cn = n0 + wn + nt * 8 + 2 * tig;
            float v0 = acc[mt][nt][0] + bias[cn];
            float v1 = acc[mt][nt][1] + bias[cn + 1];
            float v2 = acc[mt][nt][2] + bias[cn];
            float v3 = acc[mt][nt][3] + bias[cn + 1];
            if (fm) {
                v0 = (v0 > 0.f) ? (v0 + 1.f) : expf(v0);
                v1 = (v1 > 0.f) ? (v1 + 1.f) : expf(v1);
                v2 = (v2 > 0.f) ? (v2 + 1.f) : expf(v2);
                v3 = (v3 > 0.f) ? (v3 + 1.f) : expf(v3);
            }
            if (head_layout) {
                const int b = r0 >> 11, t = r0 & (TT - 1);
                const int dh = cn & 63;
                __half* p = houtp + ((size_t)((b * HH + hcol) * TT + t)) * DH + dh;
                *(uint32_t*)p            = packh2(__float2half(v0), __float2half(v1));
                *(uint32_t*)(p + 8 * DH) = packh2(__float2half(v2), __float2half(v3));
            } else {
                float* p = o0 + (size_t)r0 * DD + cn;
                *(float2*)p            = make_float2(v0, v1);
                *(float2*)(p + 8 * DD) = make_float2(v2, v3);
            }
        }
    }
}

// ---------------------------------------------------------------------------
// chunk_kv via mma: KV[d][e] = sum_t K[t][d] V[t][e]  (K^T ldsm.trans, V^T ldsm.trans)
// 128 threads / 4 warps; warp handles 16 d-rows x 64 e-cols.
// ---------------------------------------------------------------------------
__global__ __launch_bounds__(128) void chunk_kv_mma()
{
    __shared__ __half Ks[64 * SR];
    __shared__ __half Vs[64 * SR];

    const int c = blockIdx.x, bh = blockIdx.y;
    const int tid = threadIdx.x;
    const int wid = tid >> 5, lane = tid & 31;
    const int g = lane >> 2, tig = lane & 3;
    const int wm = wid * 16;

    const __half* kp = g_k + ((size_t)bh * TT + c * 64) * DH;
    const __half* vp = g_v + ((size_t)bh * TT + c * 64) * DH;
    const int lr = tid >> 1, lc = (tid & 1) * 32;
    *(uint4*)(Ks + lr * SR + lc)      = *(const uint4*)(kp + lr * 64 + lc);
    *(uint4*)(Ks + lr * SR + lc + 8)  = *(const uint4*)(kp + lr * 64 + lc + 8);
    *(uint4*)(Ks + lr * SR + lc + 16) = *(const uint4*)(kp + lr * 64 + lc + 16);
    *(uint4*)(Ks + lr * SR + lc + 24) = *(const uint4*)(kp + lr * 64 + lc + 24);
    *(uint4*)(Vs + lr * SR + lc)      = *(const uint4*)(vp + lr * 64 + lc);
    *(uint4*)(Vs + lr * SR + lc + 8)  = *(const uint4*)(vp + lr * 64 + lc + 8);
    *(uint4*)(Vs + lr * SR + lc + 16) = *(const uint4*)(vp + lr * 64 + lc + 16);
    *(uint4*)(Vs + lr * SR + lc + 24) = *(const uint4*)(vp + lr * 64 + lc + 24);
    __syncthreads();

    const uint32_t kb = smem_u32(Ks), vb = smem_u32(Vs);
    float acc[8][4];
    #pragma unroll
    for (int i = 0; i < 8; i++)
        #pragma unroll
        for (int q = 0; q < 4; q++) acc[i][q] = 0.f;

    #pragma unroll
    for (int ks = 0; ks < 4; ks++) {
        const int t0 = ks * 16;
        uint32_t ka[4];
        ldsm4t(ka, kb + (uint32_t)(t0 + ((lane >> 4) & 1) * 8 + (lane & 7)) * (SR * 2)
                     + wm * 2 + ((lane >> 3) & 1) * 16);
        #pragma unroll
        for (int ntp = 0; ntp < 4; ntp++) {
            uint32_t t[4];
            ldsm4t(t, vb + (uint32_t)(t0 + ((lane >> 3) & 1) * 8 + (lane & 7)) * (SR * 2)
                        + ntp * 32 + ((lane >> 4) & 1) * 16);
            uint32_t b0[2] = { t[0], t[1] }, b1[2] = { t[2], t[3] };
            mma16816(acc[2 * ntp],     ka, b0);
            mma16816(acc[2 * ntp + 1], ka, b1);
        }
    }

    float* kvout = g_kv + ((size_t)bh * NC + c) * 4096;
    #pragma unroll
    for (int nt = 0; nt < 8; nt++) {
        const int col = nt * 8 + 2 * tig;
        *(float2*)(kvout + (wm + g) * 64 + col)     = make_float2(acc[nt][0], acc[nt][1]);
        *(float2*)(kvout + (wm + g + 8) * 64 + col) = make_float2(acc[nt][2], acc[nt][3]);
    }

    if (tid < 64) {
        float s = 0.f;
        #pragma unroll 8
        for (int t = 0; t < 64; t++) s += __half2float(Ks[t * SR + tid]);
        g_ks[((size_t)bh * NC + c) * 64 + tid] = s;
    }
}

// ---------------------------------------------------------------------------
// Exclusive prefix scan across chunks; writes fp16 S prefix to g_sh.
// ---------------------------------------------------------------------------
__global__ __launch_bounds__(256) void prefix_scan()
{
    const int bh = blockIdx.y;
    const int p = blockIdx.x * 256 + threadIdx.x;   // 0..4095
    const float* base = g_kv + (size_t)bh * NC * 4096 + p;
    __half* outp = g_sh + (size_t)bh * NC * 4096 + p;
    float run = 0.f;
    #pragma unroll
    for (int c = 0; c < NC; c++) {
        outp[c * 4096] = __float2half(run);
        run += base[c * 4096];
    }
    if (blockIdx.x == 0 && threadIdx.x < 64) {
        float r2 = 0.f;
        float* kbp = g_ks + (size_t)bh * NC * 64 + threadIdx.x;
        #pragma unroll
        for (int c = 0; c < NC; c++) {
            float tmp = kbp[c * 64];
            kbp[c * 64] = r2;
            r2 += tmp;
        }
    }
}

// ---------------------------------------------------------------------------
// Attention chunk via mma: A = mask(QK^T); out = (A V + Q S) / (rowsum(A)+Qz)
// 128 threads / 4 warps; warp handles 16 t-rows x 64 cols.
// ---------------------------------------------------------------------------
__global__ __launch_bounds__(128) void attn_mma()
{
    __shared__ __half Qs[64 * SR];
    __shared__ __half Ks[64 * SR];   // K, then reused as A
    __shared__ __half Vs[64 * SR];
    __shared__ __half Ss[64 * SR];
    __shared__ float  zs[64];

    const int c = blockIdx.x, bh = blockIdx.y;
    const int tid = threadIdx.x;
    const int wid = tid >> 5, lane = tid & 31;
    const int g = lane >> 2, tig = lane & 3;
    const int wm = wid * 16;

    const __half* qp = g_q + ((size_t)bh * TT + c * 64) * DH;
    const __half* kp = g_k + ((size_t)bh * TT + c * 64) * DH;
    const __half* vp = g_v + ((size_t)bh * TT + c * 64) * DH;
    const __half* sp = g_sh + ((size_t)bh * NC + c) * 4096;

    const int lr = tid >> 1, lc = (tid & 1) * 32;
    #pragma unroll
    for (int u = 0; u < 4; u++) {
        *(uint4*)(Qs + lr * SR + lc + u * 8) = *(const uint4*)(qp + lr * 64 + lc + u * 8);
        *(uint4*)(Ks + lr * SR + lc + u * 8) = *(const uint4*)(kp + lr * 64 + lc + u * 8);
        *(uint4*)(Vs + lr * SR + lc + u * 8) = *(const uint4*)(vp + lr * 64 + lc + u * 8);
        *(uint4*)(Ss + lr * SR + lc + u * 8) = *(const uint4*)(sp + lr * 64 + lc + u * 8);
    }
    if (tid < 64) zs[tid] = g_ks[((size_t)bh * NC + c) * 64 + tid];
    __syncthreads();

    const uint32_t qb = smem_u32(Qs), kb = smem_u32(Ks);
    const uint32_t vb = smem_u32(Vs), sb = smem_u32(Ss);

    // ---- GEMM1: A = Q K^T (Q normal A-op; K normal B-op) ----
    float aa[8][4];
    #pragma unroll
    for (int i = 0; i < 8; i++)
        #pragma unroll
        for (int q = 0; q < 4; q++) aa[i][q] = 0.f;

    #pragma unroll
    for (int ks = 0; ks < 4; ks++) {
        const uint32_t kby = ks * 32;
        uint32_t qa[4];
        ldsm4(qa, qb + (uint32_t)(wm + ((lane >> 3) & 1) * 8 + (lane & 7)) * (SR * 2)
                    + kby + ((lane >> 4) & 1) * 16);
        #pragma unroll
        for (int ntp = 0; ntp < 4; ntp++) {
            uint32_t t[4];
            ldsm4(t, kb + (uint32_t)(ntp * 16 + ((lane >> 4) & 1) * 8 + (lane & 7)) * (SR * 2)
                       + kby + ((lane >> 3) & 1) * 16);
            uint32_t b0[2] = { t[0], t[1] }, b1[2] = { t[2], t[3] };
            mma16816(aa[2 * ntp],     qa, b0);
            mma16816(aa[2 * ntp + 1], qa, b1);
        }
    }

    // mask + rowsum
    const int r0 = wm + g, r1 = r0 + 8;
    float rs0 = 0.f, rs1 = 0.f;
    #pragma unroll
    for (int nt = 0; nt < 8; nt++) {
        const int c0 = nt * 8 + 2 * tig, c1 = c0 + 1;
        if (c0 > r0) aa[nt][0] = 0.f;
        if (c1 > r0) aa[nt][1] = 0.f;
        if (c0 > r1) aa[nt][2] = 0.f;
        if (c1 > r1) aa[nt][3] = 0.f;
        rs0 += aa[nt][0] + aa[nt][1];
        rs1 += aa[nt][2] + aa[nt][3];
    }
    #pragma unroll
    for (int off = 1; off < 4; off <<= 1) {
        rs0 += __shfl_xor_sync(0xffffffffu, rs0, off);
        rs1 += __shfl_xor_sync(0xffffffffu, rs1, off);
    }

    // qz
    float qz0 = 0.f, qz1 = 0.f;
    #pragma unroll 8
    for (int d2 = 0; d2 < 32; d2++) {
        float2 z2 = *(const float2*)(zs + 2 * d2);
        float2 q0 = __half22float2(*(const __half2*)(Qs + r0 * SR + 2 * d2));
        float2 q1 = __half22float2(*(const __half2*)(Qs + r1 * SR + 2 * d2));
        qz0 += q0.x * z2.x + q0.y * z2.y;
        qz1 += q1.x * z2.x + q1.y * z2.y;
    }

    // write masked A (fp16) into Ks
    __syncthreads();
    #pragma unroll
    for (int nt = 0; nt < 8; nt++) {
        const int col = nt * 8 + 2 * tig;
        *(uint32_t*)(Ks + r0 * SR + col) = packh2(__float2half(aa[nt][0]), __float2half(aa[nt][1]));
        *(uint32_t*)(Ks + r1 * SR + col) = packh2(__float2half(aa[nt][2]), __float2half(aa[nt][3]));
    }
    __syncthreads();

    // ---- GEMM2: out = A V (A normal; V^T via trans) + GEMM3: out += Q S (S^T via trans) ----
    float oc[8][4];
    #pragma unroll
    for (int i = 0; i < 8; i++)
        #pragma unroll
        for (int q = 0; q < 4; q++) oc[i][q] = 0.f;

    #pragma unroll
    for (int ks = 0; ks < 4; ks++) {
        const uint32_t kby = ks * 32;
        uint32_t af[4];
        ldsm4(af, kb + (uint32_t)(wm + ((lane >> 3) & 1) * 8 + (lane & 7)) * (SR * 2)
                    + kby + ((lane >> 4) & 1) * 16);
        #pragma unroll
        for (int ntp = 0; ntp < 4; ntp++) {
            uint32_t t[4];
            ldsm4t(t, vb + (uint32_t)(ks * 16 + ((lane >> 3) & 1) * 8 + (lane & 7)) * (SR * 2)
                        + ntp * 32 + ((lane >> 4) & 1) * 16);
            uint32_t b0[2] = { t[0], t[1] }, b1[2] = { t[2], t[3] };
            mma16816(oc[2 * ntp],     af, b0);
            mma16816(oc[2 * ntp + 1], af, b1);
        }
    }
    #pragma unroll
    for (int ks = 0; ks < 4; ks++) {
        const uint32_t kby = ks * 32;
        uint32_t qa[4];
        ldsm4(qa, qb + (uint32_t)(wm + ((lane >> 3) & 1) * 8 + (lane & 7)) * (SR * 2)
                    + kby + ((lane >> 4) & 1) * 16);
        #pragma unroll
        for (int ntp = 0; ntp < 4; ntp++) {
            uint32_t t[4];
            ldsm4t(t, sb + (uint32_t)(ks * 16 + ((lane >> 3) & 1) * 8 + (lane & 7)) * (SR * 2)
                        + ntp * 32 + ((lane >> 4) & 1) * 16);
            uint32_t b0[2] = { t[0], t[1] }, b1[2] = { t[2], t[3] };
            mma16816(oc[2 * ntp],     qa, b0);
            mma16816(oc[2 * ntp + 1], qa, b1);
        }
    }

    const float inv0 = 1.f / fmaxf(rs0 + qz0, EPSF);
    const float inv1 = 1.f / fmaxf(rs1 + qz1, EPSF);
    const int b = bh >> 4, h = bh & 15;
    __half* p0 = g_ah + ((size_t)(b * TT + c * 64 + r0)) * DD + h * 64;
    __half* p1 = g_ah + ((size_t)(b * TT + c * 64 + r1)) * DD + h * 64;
    #pragma unroll
    for (int nt = 0; nt < 8; nt++) {
        const int col = nt * 8 + 2 * tig;
        *(uint32_t*)(p0 + col) = packh2(__float2half(oc[nt][0] * inv0), __float2half(oc[nt][1] * inv0));
        *(uint32_t*)(p1 + col) = packh2(__float2half(oc[nt][2] * inv1), __float2half(oc[nt][3] * inv1));
    }
}

// ---------------------------------------------------------------------------
extern "C" void kernel_launch(void* const* d_in, const int* in_sizes, int n_in,
                              void* d_out, int out_size)
{
    const float* x  = (const float*)d_in[0];
    const float* Wq = (const float*)d_in[1];
    const float* bq = (const float*)d_in[2];
    const float* Wk = (const float*)d_in[3];
    const float* bk = (const float*)d_in[4];
    const float* Wv = (const float*)d_in[5];
    const float* bv = (const float*)d_in[6];
    const float* Wo = (const float*)d_in[7];
    const float* bo = (const float*)d_in[8];
    float* out = (float*)d_out;

    __half *q, *k, *v, *xh, *wh, *ah;
    cudaGetSymbolAddress((void**)&q,  g_q);
    cudaGetSymbolAddress((void**)&k,  g_k);
    cudaGetSymbolAddress((void**)&v,  g_v);
    cudaGetSymbolAddress((void**)&xh, g_xh);
    cudaGetSymbolAddress((void**)&wh, g_wh);
    cudaGetSymbolAddress((void**)&ah, g_ah);

    cudaFuncSetAttribute(mma_gemm4, cudaFuncAttributeMaxDynamicSharedMemorySize, SMEM_DYN);

    conv_all<<<(XN4 + 4 * WN4) / 256, 256>>>(x, Wq, Wk, Wv, Wo);

    // Fused Q/K/V projections (fp16 out, head layout); Q,K get the feature map.
    mma_gemm4<<<dim3(DD / BN, MM / BM, 3), 256, SMEM_DYN>>>(
        xh, wh, bq, bk, bv, nullptr, q, k, v, 1, 1, 0, /*head_layout=*/1);

    chunk_kv_mma<<<dim3(NC, BH), 128>>>();
    prefix_scan<<<dim3(16, BH), 256>>>();
    attn_mma<<<dim3(NC, BH), 128>>>();

    // Output projection (fp32 out)
    mma_gemm4<<<dim3(DD / BN, MM / BM, 1), 256, SMEM_DYN>>>(
        ah, wh + 3 * (size_t)DD * DD, bo, bo, bo, out, nullptr, nullptr, nullptr,
        0, 0, 0, /*head_layout=*/0);
}

// round 8
// speedup vs baseline: 5.9420x; 1.1059x over previous
#include <cuda_runtime.h>
#include <cuda_fp16.h>
#include <cstdint>

// Problem constants
#define BB   2
#define TT   2048
#define DD   1024
#define HH   16
#define DH   64
#define NC   32           // TT / 64 chunks
#define BH   32           // BB * HH
#define MM   4096         // BB * TT
#define EPSF 1e-6f

// GEMM tiling
#define BM   128
#define BN   128
#define BK   32
#define NKB  (DD / BK)    // 32 k-stages
#define ROWB  80          // padded row stride bytes (32 fp16 + 16B pad)
#define TILEB (128 * ROWB)
#define STG   (2 * TILEB)
#define NSTG  3
#define SMEM_DYN (NSTG * STG)

#define XN4 (MM * DD / 4)
#define WN4 (DD * DD / 4)

// attention smem row stride: 72 fp16 = 144B (conflict-free LDSM)
#define SR 72

// Scratch (device globals; allocation is forbidden)
__device__ __half g_q[BH * TT * DH];       // [b,h,t,dh] fp16
__device__ __half g_k[BH * TT * DH];
__device__ __half g_v[BH * TT * DH];
__device__ float  g_kv[BH * NC * DH * DH]; // per-chunk KV (fp32)
__device__ __half g_sh[BH * NC * DH * DH]; // exclusive-prefix S (fp16)
__device__ float  g_ks[BH * NC * DH];      // k-sum, then exclusive prefix (fp32)

// Persistent fp16 copies
__device__ __half g_xh[MM * DD];
__device__ __half g_wh[4 * DD * DD];       // Wq | Wk | Wv | Wo
__device__ __half g_ah[MM * DD];           // attention output

// ---------------------------------------------------------------------------
// helpers
// ---------------------------------------------------------------------------
__device__ __forceinline__ uint32_t smem_u32(const void* p) {
    uint32_t a;
    asm("{ .reg .u64 t; cvta.to.shared.u64 t, %1; cvt.u32.u64 %0, t; }"
        : "=r"(a) : "l"(p));
    return a;
}
__device__ __forceinline__ uint32_t packh2(__half lo, __half hi) {
    __half2 h = __halves2half2(lo, hi);
    return *(uint32_t*)&h;
}
__device__ __forceinline__ void mma16816(float* c, const uint32_t* a, const uint32_t* b) {
    asm volatile(
        "mma.sync.aligned.m16n8k16.row.col.f32.f16.f16.f32 "
        "{%0,%1,%2,%3}, {%4,%5,%6,%7}, {%8,%9}, {%0,%1,%2,%3};"
        : "+f"(c[0]), "+f"(c[1]), "+f"(c[2]), "+f"(c[3])
        : "r"(a[0]), "r"(a[1]), "r"(a[2]), "r"(a[3]), "r"(b[0]), "r"(b[1]));
}
__device__ __forceinline__ void ldsm4(uint32_t* r, uint32_t addr) {
    asm volatile("ldmatrix.sync.aligned.m8n8.x4.shared.b16 {%0,%1,%2,%3}, [%4];"
                 : "=r"(r[0]), "=r"(r[1]), "=r"(r[2]), "=r"(r[3]) : "r"(addr));
}
__device__ __forceinline__ void ldsm4t(uint32_t* r, uint32_t addr) {
    asm volatile("ldmatrix.sync.aligned.m8n8.x4.trans.shared.b16 {%0,%1,%2,%3}, [%4];"
                 : "=r"(r[0]), "=r"(r[1]), "=r"(r[2]), "=r"(r[3]) : "r"(addr));
}
__device__ __forceinline__ void cp16(uint32_t dst, const void* src) {
    asm volatile("cp.async.cg.shared.global [%0], [%1], 16;"
                 :: "r"(dst), "l"(src) : "memory");
}
#define CP_COMMIT() asm volatile("cp.async.commit_group;" ::: "memory")
#define CP_WAIT1()  asm volatile("cp.async.wait_group 1;"  ::: "memory")

// ---------------------------------------------------------------------------
// Fused one-time fp32 -> fp16 cast: x then Wq/Wk/Wv/Wo
// ---------------------------------------------------------------------------
__global__ __launch_bounds__(256) void conv_all(
    const float* __restrict__ x,
    const float* __restrict__ Wq, const float* __restrict__ Wk,
    const float* __restrict__ Wv, const float* __restrict__ Wo)
{
    const int i = blockIdx.x * 256 + threadIdx.x;
    const float* src;
    __half* dst;
    int j;
    if (i < XN4) {
        src = x; dst = g_xh; j = i;
    } else {
        const int t = i - XN4;
        const int w = t / WN4;
        j = t - w * WN4;
        src = (w == 0) ? Wq : (w == 1) ? Wk : (w == 2) ? Wv : Wo;
        dst = g_wh + (size_t)w * DD * DD;
    }
    float4 v = ((const float4*)src)[j];
    uint2 u;
    u.x = packh2(__float2half(v.x), __float2half(v.y));
    u.y = packh2(__float2half(v.z), __float2half(v.w));
    ((uint2*)dst)[j] = u;
}

// ---------------------------------------------------------------------------
// fp16 tensor-core GEMM. head_layout: write fp16 to hq/hk/hv in [b,h,t,dh];
// else write fp32 to o0 in [m][n]. 2 CTAs/SM for wave packing.
// ---------------------------------------------------------------------------
__global__ __launch_bounds__(256, 2) void mma_gemm4(
    const __half* __restrict__ A, const __half* __restrict__ W,
    const float* __restrict__ bz0, const float* __restrict__ bz1, const float* __restrict__ bz2,
    float* __restrict__ o0,
    __half* __restrict__ h0, __half* __restrict__ h1, __half* __restrict__ h2,
    int f0, int f1, int f2, int head_layout)
{
    extern __shared__ char dsm[];

    const int z = blockIdx.z;
    const __half* B = W + (size_t)z * DD * DD;
    const float* bias = (z == 0) ? bz0 : (z == 1) ? bz1 : bz2;
    __half*      houtp = (z == 0) ? h0 : (z == 1) ? h1 : h2;
    const int    fm   = (z == 0) ? f0  : (z == 1) ? f1  : f2;

    const int tid  = threadIdx.x;
    const int wid  = tid >> 5, lane = tid & 31;
    const int m0   = blockIdx.y * BM, n0 = blockIdx.x * BN;
    const int wm   = (wid >> 2) * 64, wn = (wid & 3) * 32;
    const int g    = lane >> 2, tig = lane & 3;
    const uint32_t sb = smem_u32(dsm);

    float acc[4][4][4];
    #pragma unroll
    for (int i = 0; i < 4; i++)
        #pragma unroll
        for (int j = 0; j < 4; j++)
            #pragma unroll
            for (int q = 0; q < 4; q++) acc[i][j][q] = 0.f;

    const int srow = tid >> 1;
    const int scol = (tid & 1) * 16;
    const uint32_t doff = (uint32_t)srow * ROWB + scol * 2;

    auto issue = [&](int c, int s) {
        const uint32_t base = sb + s * STG;
        const int kb = c * BK;
        const __half* ap = A + (size_t)(m0 + srow) * DD + kb + scol;
        const __half* bp = B + (size_t)(n0 + srow) * DD + kb + scol;
        cp16(base + doff,              ap);
        cp16(base + doff + 16,         ap + 8);
        cp16(base + TILEB + doff,      bp);
        cp16(base + TILEB + doff + 16, bp + 8);
    };

    auto compute = [&](int s) {
        const uint32_t base = sb + s * STG;
        #pragma unroll
        for (int kt = 0; kt < 2; kt++) {
            const uint32_t kby = kt * 32;
            uint32_t bf[4][2];
            #pragma unroll
            for (int ntp = 0; ntp < 2; ntp++) {
                const uint32_t baddr = base + TILEB +
                    (uint32_t)(wn + ntp * 16 + ((lane >> 4) & 1) * 8 + (lane & 7)) * ROWB +
                    kby + ((lane >> 3) & 1) * 16;
                uint32_t t[4];
                ldsm4(t, baddr);
                bf[2 * ntp][0] = t[0];     bf[2 * ntp][1] = t[1];
                bf[2 * ntp + 1][0] = t[2]; bf[2 * ntp + 1][1] = t[3];
            }
            #pragma unroll
            for (int mt = 0; mt < 4; mt++) {
                const uint32_t aaddr = base +
                    (uint32_t)(wm + mt * 16 + ((lane >> 3) & 1) * 8 + (lane & 7)) * ROWB +
                    kby + ((lane >> 4) & 1) * 16;
                uint32_t af[4];
                ldsm4(af, aaddr);
                #pragma unroll
                for (int nt = 0; nt < 4; nt++)
                    mma16816(acc[mt][nt], af, bf[nt]);
            }
        }
    };

    issue(0, 0); CP_COMMIT();
    issue(1, 1); CP_COMMIT();

    for (int c = 0; c < NKB; c++) {
        CP_WAIT1();
        __syncthreads();
        compute(c % NSTG);
        if (c + 2 < NKB) issue(c + 2, (c + 2) % NSTG);
        CP_COMMIT();
    }

    const int hcol = (n0 + wn) >> 6;
    #pragma unroll
    for (int mt = 0; mt < 4; mt++) {
        const int r0 = m0 + wm + mt * 16 + g;
        #pragma unroll
        for (int nt = 0; nt < 4; nt++) {
            const int cn = n0 + wn + nt * 8 + 2 * tig;
            float v0 = acc[mt][nt][0] + bias[cn];
            float v1 = acc[mt][nt][1] + bias[cn + 1];
            float v2 = acc[mt][nt][2] + bias[cn];
            float v3 = acc[mt][nt][3] + bias[cn + 1];
            if (fm) {
                v0 = (v0 > 0.f) ? (v0 + 1.f) : expf(v0);
                v1 = (v1 > 0.f) ? (v1 + 1.f) : expf(v1);
                v2 = (v2 > 0.f) ? (v2 + 1.f) : expf(v2);
                v3 = (v3 > 0.f) ? (v3 + 1.f) : expf(v3);
            }
            if (head_layout) {
                const int b = r0 >> 11, t = r0 & (TT - 1);
                const int dh = cn & 63;
                __half* p = houtp + ((size_t)((b * HH + hcol) * TT + t)) * DH + dh;
                *(uint32_t*)p            = packh2(__float2half(v0), __float2half(v1));
                *(uint32_t*)(p + 8 * DH) = packh2(__float2half(v2), __float2half(v3));
            } else {
                float* p = o0 + (size_t)r0 * DD + cn;
                *(float2*)p            = make_float2(v0, v1);
                *(float2*)(p + 8 * DD) = make_float2(v2, v3);
            }
        }
    }
}

// ---------------------------------------------------------------------------
// chunk_kv via mma: KV[d][e] = sum_t K[t][d] V[t][e]
// ---------------------------------------------------------------------------
__global__ __launch_bounds__(128) void chunk_kv_mma()
{
    __shared__ __half Ks[64 * SR];
    __shared__ __half Vs[64 * SR];

    const int c = blockIdx.x, bh = blockIdx.y;
    const int tid = threadIdx.x;
    const int wid = tid >> 5, lane = tid & 31;
    const int g = lane >> 2, tig = lane & 3;
    const int wm = wid * 16;

    const __half* kp = g_k + ((size_t)bh * TT + c * 64) * DH;
    const __half* vp = g_v + ((size_t)bh * TT + c * 64) * DH;
    const int lr = tid >> 1, lc = (tid & 1) * 32;
    #pragma unroll
    for (int u = 0; u < 4; u++) {
        *(uint4*)(Ks + lr * SR + lc + u * 8) = *(const uint4*)(kp + lr * 64 + lc + u * 8);
        *(uint4*)(Vs + lr * SR + lc + u * 8) = *(const uint4*)(vp + lr * 64 + lc + u * 8);
    }
    __syncthreads();

    const uint32_t kb = smem_u32(Ks), vb = smem_u32(Vs);
    float acc[8][4];
    #pragma unroll
    for (int i = 0; i < 8; i++)
        #pragma unroll
        for (int q = 0; q < 4; q++) acc[i][q] = 0.f;

    #pragma unroll
    for (int ks = 0; ks < 4; ks++) {
        const int t0 = ks * 16;
        uint32_t ka[4];
        ldsm4t(ka, kb + (uint32_t)(t0 + ((lane >> 4) & 1) * 8 + (lane & 7)) * (SR * 2)
                     + wm * 2 + ((lane >> 3) & 1) * 16);
        #pragma unroll
        for (int ntp = 0; ntp < 4; ntp++) {
            uint32_t t[4];
            ldsm4t(t, vb + (uint32_t)(t0 + ((lane >> 3) & 1) * 8 + (lane & 7)) * (SR * 2)
                        + ntp * 32 + ((lane >> 4) & 1) * 16);
            uint32_t b0[2] = { t[0], t[1] }, b1[2] = { t[2], t[3] };
            mma16816(acc[2 * ntp],     ka, b0);
            mma16816(acc[2 * ntp + 1], ka, b1);
        }
    }

    float* kvout = g_kv + ((size_t)bh * NC + c) * 4096;
    #pragma unroll
    for (int nt = 0; nt < 8; nt++) {
        const int col = nt * 8 + 2 * tig;
        *(float2*)(kvout + (wm + g) * 64 + col)     = make_float2(acc[nt][0], acc[nt][1]);
        *(float2*)(kvout + (wm + g + 8) * 64 + col) = make_float2(acc[nt][2], acc[nt][3]);
    }

    if (tid < 64) {
        float s = 0.f;
        #pragma unroll 8
        for (int t = 0; t < 64; t++) s += __half2float(Ks[t * SR + tid]);
        g_ks[((size_t)bh * NC + c) * 64 + tid] = s;
    }
}

// ---------------------------------------------------------------------------
// Exclusive prefix scan across chunks; register-prefetched (MLP=32).
// Writes fp16 S prefix to g_sh.
// ---------------------------------------------------------------------------
__global__ __launch_bounds__(256) void prefix_scan()
{
    const int bh = blockIdx.y;
    const int p = blockIdx.x * 256 + threadIdx.x;   // 0..4095
    const float* base = g_kv + (size_t)bh * NC * 4096 + p;
    __half* outp = g_sh + (size_t)bh * NC * 4096 + p;

    float v[NC];
    #pragma unroll
    for (int c = 0; c < NC; c++) v[c] = base[c * 4096];   // independent loads
    float run = 0.f;
    #pragma unroll
    for (int c = 0; c < NC; c++) {
        outp[c * 4096] = __float2half(run);
        run += v[c];
    }

    if (blockIdx.x == 0 && threadIdx.x < 64) {
        float w[NC];
        float* kbp = g_ks + (size_t)bh * NC * 64 + threadIdx.x;
        #pragma unroll
        for (int c = 0; c < NC; c++) w[c] = kbp[c * 64];
        float r2 = 0.f;
        #pragma unroll
        for (int c = 0; c < NC; c++) {
            kbp[c * 64] = r2;
            r2 += w[c];
        }
    }
}

// ---------------------------------------------------------------------------
// Attention chunk via mma: A = mask(QK^T); out = (A V + Q S) / (rowsum(A)+Qz)
// ---------------------------------------------------------------------------
__global__ __launch_bounds__(128) void attn_mma()
{
    __shared__ __half Qs[64 * SR];
    __shared__ __half Ks[64 * SR];   // K, then reused as A
    __shared__ __half Vs[64 * SR];
    __shared__ __half Ss[64 * SR];
    __shared__ float  zs[64];

    const int c = blockIdx.x, bh = blockIdx.y;
    const int tid = threadIdx.x;
    const int wid = tid >> 5, lane = tid & 31;
    const int g = lane >> 2, tig = lane & 3;
    const int wm = wid * 16;

    const __half* qp = g_q + ((size_t)bh * TT + c * 64) * DH;
    const __half* kp = g_k + ((size_t)bh * TT + c * 64) * DH;
    const __half* vp = g_v + ((size_t)bh * TT + c * 64) * DH;
    const __half* sp = g_sh + ((size_t)bh * NC + c) * 4096;

    const int lr = tid >> 1, lc = (tid & 1) * 32;
    #pragma unroll
    for (int u = 0; u < 4; u++) {
        *(uint4*)(Qs + lr * SR + lc + u * 8) = *(const uint4*)(qp + lr * 64 + lc + u * 8);
        *(uint4*)(Ks + lr * SR + lc + u * 8) = *(const uint4*)(kp + lr * 64 + lc + u * 8);
        *(uint4*)(Vs + lr * SR + lc + u * 8) = *(const uint4*)(vp + lr * 64 + lc + u * 8);
        *(uint4*)(Ss + lr * SR + lc + u * 8) = *(const uint4*)(sp + lr * 64 + lc + u * 8);
    }
    if (tid < 64) zs[tid] = g_ks[((size_t)bh * NC + c) * 64 + tid];
    __syncthreads();

    const uint32_t qb = smem_u32(Qs), kb = smem_u32(Ks);
    const uint32_t vb = smem_u32(Vs), sb = smem_u32(Ss);

    // ---- GEMM1: A = Q K^T ----
    float aa[8][4];
    #pragma unroll
    for (int i = 0; i < 8; i++)
        #pragma unroll
        for (int q = 0; q < 4; q++) aa[i][q] = 0.f;

    #pragma unroll
    for (int ks = 0; ks < 4; ks++) {
        const uint32_t kby = ks * 32;
        uint32_t qa[4];
        ldsm4(qa, qb + (uint32_t)(wm + ((lane >> 3) & 1) * 8 + (lane & 7)) * (SR * 2)
                    + kby + ((lane >> 4) & 1) * 16);
        #pragma unroll
        for (int ntp = 0; ntp < 4; ntp++) {
            uint32_t t[4];
            ldsm4(t, kb + (uint32_t)(ntp * 16 + ((lane >> 4) & 1) * 8 + (lane & 7)) * (SR * 2)
                       + kby + ((lane >> 3) & 1) * 16);
            uint32_t b0[2] = { t[0], t[1] }, b1[2] = { t[2], t[3] };
            mma16816(aa[2 * ntp],     qa, b0);
            mma16816(aa[2 * ntp + 1], qa, b1);
        }
    }

    // mask + rowsum
    const int r0 = wm + g, r1 = r0 + 8;
    float rs0 = 0.f, rs1 = 0.f;
    #pragma unroll
    for (int nt = 0; nt < 8; nt++) {
        const int c0 = nt * 8 + 2 * tig, c1 = c0 + 1;
        if (c0 > r0) aa[nt][0] = 0.f;
        if (c1 > r0) aa[nt][1] = 0.f;
        if (c0 > r1) aa[nt][2] = 0.f;
        if (c1 > r1) aa[nt][3] = 0.f;
        rs0 += aa[nt][0] + aa[nt][1];
        rs1 += aa[nt][2] + aa[nt][3];
    }
    #pragma unroll
    for (int off = 1; off < 4; off <<= 1) {
        rs0 += __shfl_xor_sync(0xffffffffu, rs0, off);
        rs1 += __shfl_xor_sync(0xffffffffu, rs1, off);
    }

    // qz
    float qz0 = 0.f, qz1 = 0.f;
    #pragma unroll 8
    for (int d2 = 0; d2 < 32; d2++) {
        float2 z2 = *(const float2*)(zs + 2 * d2);
        float2 q0 = __half22float2(*(const __half2*)(Qs + r0 * SR + 2 * d2));
        float2 q1 = __half22float2(*(const __half2*)(Qs + r1 * SR + 2 * d2));
        qz0 += q0.x * z2.x + q0.y * z2.y;
        qz1 += q1.x * z2.x + q1.y * z2.y;
    }

    // write masked A (fp16) into Ks
    __syncthreads();
    #pragma unroll
    for (int nt = 0; nt < 8; nt++) {
        const int col = nt * 8 + 2 * tig;
        *(uint32_t*)(Ks + r0 * SR + col) = packh2(__float2half(aa[nt][0]), __float2half(aa[nt][1]));
        *(uint32_t*)(Ks + r1 * SR + col) = packh2(__float2half(aa[nt][2]), __float2half(aa[nt][3]));
    }
    __syncthreads();

    // ---- GEMM2: out = A V + GEMM3: out += Q S ----
    float oc[8][4];
    #pragma unroll
    for (int i = 0; i < 8; i++)
        #pragma unroll
        for (int q = 0; q < 4; q++) oc[i][q] = 0.f;

    #pragma unroll
    for (int ks = 0; ks < 4; ks++) {
        const uint32_t kby = ks * 32;
        uint32_t af[4];
        ldsm4(af, kb + (uint32_t)(wm + ((lane >> 3) & 1) * 8 + (lane & 7)) * (SR * 2)
                    + kby + ((lane >> 4) & 1) * 16);
        #pragma unroll
        for (int ntp = 0; ntp < 4; ntp++) {
            uint32_t t[4];
            ldsm4t(t, vb + (uint32_t)(ks * 16 + ((lane >> 3) & 1) * 8 + (lane & 7)) * (SR * 2)
                        + ntp * 32 + ((lane >> 4) & 1) * 16);
            uint32_t b0[2] = { t[0], t[1] }, b1[2] = { t[2], t[3] };
            mma16816(oc[2 * ntp],     af, b0);
            mma16816(oc[2 * ntp + 1], af, b1);
        }
    }
    #pragma unroll
    for (int ks = 0; ks < 4; ks++) {
        const uint32_t kby = ks * 32;
        uint32_t qa[4];
        ldsm4(qa, qb + (uint32_t)(wm + ((lane >> 3) & 1) * 8 + (lane & 7)) * (SR * 2)
                    + kby + ((lane >> 4) & 1) * 16);
        #pragma unroll
        for (int ntp = 0; ntp < 4; ntp++) {
            uint32_t t[4];
            ldsm4t(t, sb + (uint32_t)(ks * 16 + ((lane >> 3) & 1) * 8 + (lane & 7)) * (SR * 2)
                        + ntp * 32 + ((lane >> 4) & 1) * 16);
            uint32_t b0[2] = { t[0], t[1] }, b1[2] = { t[2], t[3] };
            mma16816(oc[2 * ntp],     qa, b0);
            mma16816(oc[2 * ntp + 1], qa, b1);
        }
    }

    const float inv0 = 1.f / fmaxf(rs0 + qz0, EPSF);
    const float inv1 = 1.f / fmaxf(rs1 + qz1, EPSF);
    const int b = bh >> 4, h = bh & 15;
    __half* p0 = g_ah + ((size_t)(b * TT + c * 64 + r0)) * DD + h * 64;
    __half* p1 = g_ah + ((size_t)(b * TT + c * 64 + r1)) * DD + h * 64;
    #pragma unroll
    for (int nt = 0; nt < 8; nt++) {
        const int col = nt * 8 + 2 * tig;
        *(uint32_t*)(p0 + col) = packh2(__float2half(oc[nt][0] * inv0), __float2half(oc[nt][1] * inv0));
        *(uint32_t*)(p1 + col) = packh2(__float2half(oc[nt][2] * inv1), __float2half(oc[nt][3] * inv1));
    }
}

// ---------------------------------------------------------------------------
extern "C" void kernel_launch(void* const* d_in, const int* in_sizes, int n_in,
                              void* d_out, int out_size)
{
    const float* x  = (const float*)d_in[0];
    const float* Wq = (const float*)d_in[1];
    const float* bq = (const float*)d_in[2];
    const float* Wk = (const float*)d_in[3];
    const float* bk = (const float*)d_in[4];
    const float* Wv = (const float*)d_in[5];
    const float* bv = (const float*)d_in[6];
    const float* Wo = (const float*)d_in[7];
    const float* bo = (const float*)d_in[8];
    float* out = (float*)d_out;

    __half *q, *k, *v, *xh, *wh, *ah;
    cudaGetSymbolAddress((void**)&q,  g_q);
    cudaGetSymbolAddress((void**)&k,  g_k);
    cudaGetSymbolAddress((void**)&v,  g_v);
    cudaGetSymbolAddress((void**)&xh, g_xh);
    cudaGetSymbolAddress((void**)&wh, g_wh);
    cudaGetSymbolAddress((void**)&ah, g_ah);

    cudaFuncSetAttribute(mma_gemm4, cudaFuncAttributeMaxDynamicSharedMemorySize, SMEM_DYN);

    conv_all<<<(XN4 + 4 * WN4) / 256, 256>>>(x, Wq, Wk, Wv, Wo);

    // Fused Q/K/V projections (fp16 out, head layout); Q,K get the feature map.
    mma_gemm4<<<dim3(DD / BN, MM / BM, 3), 256, SMEM_DYN>>>(
        xh, wh, bq, bk, bv, nullptr, q, k, v, 1, 1, 0, /*head_layout=*/1);

    chunk_kv_mma<<<dim3(NC, BH), 128>>>();
    prefix_scan<<<dim3(16, BH), 256>>>();
    attn_mma<<<dim3(NC, BH), 128>>>();

    // Output projection (fp32 out)
    mma_gemm4<<<dim3(DD / BN, MM / BM, 1), 256, SMEM_DYN>>>(
        ah, wh + 3 * (size_t)DD * DD, bo, bo, bo, out, nullptr, nullptr, nullptr,
        0, 0, 0, /*head_layout=*/0);
}